// round 1
// baseline (speedup 1.0000x reference)
#include <cuda_runtime.h>
#include <cuda_bf16.h>
#include <cstdint>

// Problem constants
#define B_  2
#define T_  2048
#define D_  1024
#define H_  16
#define HD_ 64
#define M_ROWS (B_ * T_)   // 4096

// Scratch (allocation-free rule: __device__ globals)
__device__ float g_qkv[(size_t)B_ * T_ * 3 * D_];  // [B,T,3D] 50.3 MB
__device__ float g_y[(size_t)B_ * T_ * D_];        // [B,T,D]  16.8 MB

// ---------------------------------------------------------------------------
// SGEMM: C[M,N] = A[M,K] @ B[N,K]^T   (both row-major; B stored [N,K])
// 128x128 tile, BK=16, 256 threads, 8x8 per thread (4+4 interleaved frags)
// ---------------------------------------------------------------------------
template <int M, int N, int K, bool C_IS_QKV, bool A_IS_Y>
__global__ __launch_bounds__(256, 2) void sgemm_nt_kernel(
    const float* __restrict__ Aarg, const float* __restrict__ Barg,
    float* __restrict__ Carg)
{
    constexpr int BK = 16;
    __shared__ float As[BK][132];
    __shared__ float Bs[BK][132];

    const float* __restrict__ A = A_IS_Y ? (const float*)g_y : Aarg;
    float* __restrict__ C = C_IS_QKV ? (float*)g_qkv : Carg;
    const float* __restrict__ Bm = Barg;

    const int tid = threadIdx.x;
    const int tx = tid & 15;        // 0..15 -> N frags
    const int ty = tid >> 4;        // 0..15 -> M frags
    const int m0 = blockIdx.y * 128;
    const int n0 = blockIdx.x * 128;

    float acc[8][8];
#pragma unroll
    for (int i = 0; i < 8; i++)
#pragma unroll
        for (int j = 0; j < 8; j++) acc[i][j] = 0.f;

    const float* Ab = A + (size_t)m0 * K;
    const float* Bb = Bm + (size_t)n0 * K;

    for (int k0 = 0; k0 < K; k0 += BK) {
        // 128 rows x 16 cols = 512 float4 slots; each thread does 2
#pragma unroll
        for (int i = 0; i < 2; i++) {
            int s = tid + i * 256;
            int row = s >> 2;
            int kc = (s & 3) * 4;
            float4 av = *(const float4*)(Ab + (size_t)row * K + k0 + kc);
            float4 bv = *(const float4*)(Bb + (size_t)row * K + k0 + kc);
            As[kc + 0][row] = av.x; As[kc + 1][row] = av.y;
            As[kc + 2][row] = av.z; As[kc + 3][row] = av.w;
            Bs[kc + 0][row] = bv.x; Bs[kc + 1][row] = bv.y;
            Bs[kc + 2][row] = bv.z; Bs[kc + 3][row] = bv.w;
        }
        __syncthreads();

#pragma unroll
        for (int k = 0; k < BK; k++) {
            float4 a0 = *(const float4*)&As[k][ty * 4];
            float4 a1 = *(const float4*)&As[k][64 + ty * 4];
            float4 b0 = *(const float4*)&Bs[k][tx * 4];
            float4 b1 = *(const float4*)&Bs[k][64 + tx * 4];
            float a[8] = {a0.x, a0.y, a0.z, a0.w, a1.x, a1.y, a1.z, a1.w};
            float b[8] = {b0.x, b0.y, b0.z, b0.w, b1.x, b1.y, b1.z, b1.w};
#pragma unroll
            for (int i = 0; i < 8; i++)
#pragma unroll
                for (int j = 0; j < 8; j++) acc[i][j] += a[i] * b[j];
        }
        __syncthreads();
    }

#pragma unroll
    for (int i = 0; i < 8; i++) {
        int rg = m0 + ((i < 4) ? (ty * 4 + i) : (64 + ty * 4 + i - 4));
        float4 c0 = make_float4(acc[i][0], acc[i][1], acc[i][2], acc[i][3]);
        float4 c1 = make_float4(acc[i][4], acc[i][5], acc[i][6], acc[i][7]);
        *(float4*)(C + (size_t)rg * N + n0 + tx * 4) = c0;
        *(float4*)(C + (size_t)rg * N + n0 + 64 + tx * 4) = c1;
    }
}

// ---------------------------------------------------------------------------
// Flash attention (causal), fp32.
// grid: (T/64, B*H). block: 256 threads. Each block: 64 q-rows of one head.
// Thread (r = tid/4, q4 = tid%4): S cols c = q4 + 4*cc (cc<16),
//                                 O dims d = q4*16 + dd (dd<16).
// smem: Q,K,V,P tiles [64][68] (dynamic, 69632 B).
// ---------------------------------------------------------------------------
__global__ __launch_bounds__(256) void attn_kernel()
{
    extern __shared__ float sm[];
    float (*Qs)[68] = (float(*)[68])(sm);
    float (*Ks)[68] = (float(*)[68])(sm + 64 * 68);
    float (*Vs)[68] = (float(*)[68])(sm + 2 * 64 * 68);
    float (*Ps)[68] = (float(*)[68])(sm + 3 * 64 * 68);

    const int tid = threadIdx.x;
    const int r = tid >> 2;     // 0..63 local q row
    const int q4 = tid & 3;     // quad lane
    const int it = blockIdx.x;  // q tile index
    const int bh = blockIdx.y;
    const int b = bh >> 4;
    const int h = bh & 15;

    const float* base = g_qkv + (size_t)b * T_ * (3 * D_) + h * HD_;
    const int qrow = it * 64 + r;
    const float scale = 0.125f;  // 1/sqrt(64)

    // Load Q tile [64 x 64]
    for (int s = tid; s < 64 * 16; s += 256) {
        int rr = s >> 4;
        int c4 = (s & 15) * 4;
        float4 v = *(const float4*)(base + (size_t)(it * 64 + rr) * (3 * D_) + c4);
        Qs[rr][c4] = v.x; Qs[rr][c4 + 1] = v.y; Qs[rr][c4 + 2] = v.z; Qs[rr][c4 + 3] = v.w;
    }

    float m = -1e30f, l = 0.f;
    float o[16];
#pragma unroll
    for (int i = 0; i < 16; i++) o[i] = 0.f;

    for (int j = 0; j <= it; j++) {
        __syncthreads();
        // Load K, V tiles [64 x 64]
        for (int s = tid; s < 64 * 16; s += 256) {
            int rr = s >> 4;
            int c4 = (s & 15) * 4;
            const float* kp = base + D_ + (size_t)(j * 64 + rr) * (3 * D_) + c4;
            float4 kv = *(const float4*)kp;
            float4 vv = *(const float4*)(kp + D_);
            Ks[rr][c4] = kv.x; Ks[rr][c4 + 1] = kv.y; Ks[rr][c4 + 2] = kv.z; Ks[rr][c4 + 3] = kv.w;
            Vs[rr][c4] = vv.x; Vs[rr][c4 + 1] = vv.y; Vs[rr][c4 + 2] = vv.z; Vs[rr][c4 + 3] = vv.w;
        }
        __syncthreads();

        // S = Q K^T for cols c = q4 + 4*cc
        float sv[16];
#pragma unroll
        for (int cc = 0; cc < 16; cc++) sv[cc] = 0.f;
#pragma unroll
        for (int d4 = 0; d4 < 16; d4++) {
            float4 qv = *(const float4*)&Qs[r][d4 * 4];
#pragma unroll
            for (int cc = 0; cc < 16; cc++) {
                float4 kv = *(const float4*)&Ks[q4 + cc * 4][d4 * 4];
                sv[cc] += qv.x * kv.x + qv.y * kv.y + qv.z * kv.z + qv.w * kv.w;
            }
        }

        // scale + causal mask + row max (quad reduce)
        float mx = -1e30f;
#pragma unroll
        for (int cc = 0; cc < 16; cc++) {
            int cg = j * 64 + q4 + cc * 4;
            float v = sv[cc] * scale;
            if (cg > qrow) v = -1e30f;
            sv[cc] = v;
            mx = fmaxf(mx, v);
        }
        mx = fmaxf(mx, __shfl_xor_sync(0xffffffffu, mx, 1));
        mx = fmaxf(mx, __shfl_xor_sync(0xffffffffu, mx, 2));
        float m_new = fmaxf(m, mx);
        float corr = __expf(m - m_new);

        float ls = 0.f;
#pragma unroll
        for (int cc = 0; cc < 16; cc++) {
            float p = __expf(sv[cc] - m_new);
            Ps[r][q4 + cc * 4] = p;
            ls += p;
        }
        ls += __shfl_xor_sync(0xffffffffu, ls, 1);
        ls += __shfl_xor_sync(0xffffffffu, ls, 2);
        l = l * corr + ls;
        m = m_new;
#pragma unroll
        for (int i = 0; i < 16; i++) o[i] *= corr;

        __syncwarp();

        // O += P V for dims d = q4*16 + dd
#pragma unroll
        for (int c = 0; c < 64; c++) {
            float p = Ps[r][c];
            const float4* vp = (const float4*)&Vs[c][q4 * 16];
            float4 v0 = vp[0], v1 = vp[1], v2 = vp[2], v3 = vp[3];
            o[0]  += p * v0.x; o[1]  += p * v0.y; o[2]  += p * v0.z; o[3]  += p * v0.w;
            o[4]  += p * v1.x; o[5]  += p * v1.y; o[6]  += p * v1.z; o[7]  += p * v1.w;
            o[8]  += p * v2.x; o[9]  += p * v2.y; o[10] += p * v2.z; o[11] += p * v2.w;
            o[12] += p * v3.x; o[13] += p * v3.y; o[14] += p * v3.z; o[15] += p * v3.w;
        }
    }

    // y[b, qrow, h*64 + q4*16 + dd] = o/l
    float inv = 1.f / l;
    float* yp = g_y + ((size_t)b * T_ + qrow) * D_ + h * HD_ + q4 * 16;
#pragma unroll
    for (int i = 0; i < 4; i++) {
        float4 v = make_float4(o[i * 4] * inv, o[i * 4 + 1] * inv,
                               o[i * 4 + 2] * inv, o[i * 4 + 3] * inv);
        *(float4*)(yp + i * 4) = v;
    }
}

// ---------------------------------------------------------------------------
extern "C" void kernel_launch(void* const* d_in, const int* in_sizes, int n_in,
                              void* d_out, int out_size)
{
    const float* x      = (const float*)d_in[0];
    const float* w_qkv  = (const float*)d_in[1];
    const float* w_proj = (const float*)d_in[2];
    float* out = (float*)d_out;

    // QKV GEMM: [4096,1024] @ [3072,1024]^T -> g_qkv [4096,3072]
    {
        dim3 grid(3 * D_ / 128, M_ROWS / 128);
        sgemm_nt_kernel<M_ROWS, 3 * D_, D_, true, false><<<grid, 256>>>(x, w_qkv, nullptr);
    }

    // Attention -> g_y
    {
        cudaFuncSetAttribute(attn_kernel, cudaFuncAttributeMaxDynamicSharedMemorySize,
                             4 * 64 * 68 * sizeof(float));
        dim3 grid(T_ / 64, B_ * H_);
        attn_kernel<<<grid, 256, 4 * 64 * 68 * sizeof(float)>>>();
    }

    // Proj GEMM: g_y [4096,1024] @ [1024,1024]^T -> out
    {
        dim3 grid(D_ / 128, M_ROWS / 128);
        sgemm_nt_kernel<M_ROWS, D_, D_, false, true><<<grid, 256>>>(nullptr, w_proj, out);
    }
}

// round 2
// speedup vs baseline: 1.8254x; 1.8254x over previous
#include <cuda_runtime.h>
#include <cuda_bf16.h>
#include <cstdint>

// Problem constants
#define B_  2
#define T_  2048
#define D_  1024
#define H_  16
#define HD_ 64
#define M_ROWS (B_ * T_)   // 4096

// Scratch (allocation-free rule: __device__ globals)
__device__ float g_qkv[(size_t)B_ * T_ * 3 * D_];  // [B,T,3D] 50.3 MB
__device__ float g_y[(size_t)B_ * T_ * D_];        // [B,T,D]  16.8 MB

// ---------------------------------------------------------------------------
// SGEMM: C[M,N] = A[M,K] @ B[N,K]^T   (both row-major; B stored [N,K])
// 128x128 tile, BK=16, 256 threads, 8x8 per thread (4+4 interleaved frags)
// Measured at the fp32 FFMA floor (fma=54.9%); unchanged this round.
// ---------------------------------------------------------------------------
template <int M, int N, int K, bool C_IS_QKV, bool A_IS_Y>
__global__ __launch_bounds__(256, 2) void sgemm_nt_kernel(
    const float* __restrict__ Aarg, const float* __restrict__ Barg,
    float* __restrict__ Carg)
{
    constexpr int BK = 16;
    __shared__ float As[BK][132];
    __shared__ float Bs[BK][132];

    const float* __restrict__ A = A_IS_Y ? (const float*)g_y : Aarg;
    float* __restrict__ C = C_IS_QKV ? (float*)g_qkv : Carg;
    const float* __restrict__ Bm = Barg;

    const int tid = threadIdx.x;
    const int tx = tid & 15;        // 0..15 -> N frags
    const int ty = tid >> 4;        // 0..15 -> M frags
    const int m0 = blockIdx.y * 128;
    const int n0 = blockIdx.x * 128;

    float acc[8][8];
#pragma unroll
    for (int i = 0; i < 8; i++)
#pragma unroll
        for (int j = 0; j < 8; j++) acc[i][j] = 0.f;

    const float* Ab = A + (size_t)m0 * K;
    const float* Bb = Bm + (size_t)n0 * K;

    for (int k0 = 0; k0 < K; k0 += BK) {
#pragma unroll
        for (int i = 0; i < 2; i++) {
            int s = tid + i * 256;
            int row = s >> 2;
            int kc = (s & 3) * 4;
            float4 av = *(const float4*)(Ab + (size_t)row * K + k0 + kc);
            float4 bv = *(const float4*)(Bb + (size_t)row * K + k0 + kc);
            As[kc + 0][row] = av.x; As[kc + 1][row] = av.y;
            As[kc + 2][row] = av.z; As[kc + 3][row] = av.w;
            Bs[kc + 0][row] = bv.x; Bs[kc + 1][row] = bv.y;
            Bs[kc + 2][row] = bv.z; Bs[kc + 3][row] = bv.w;
        }
        __syncthreads();

#pragma unroll
        for (int k = 0; k < BK; k++) {
            float4 a0 = *(const float4*)&As[k][ty * 4];
            float4 a1 = *(const float4*)&As[k][64 + ty * 4];
            float4 b0 = *(const float4*)&Bs[k][tx * 4];
            float4 b1 = *(const float4*)&Bs[k][64 + tx * 4];
            float a[8] = {a0.x, a0.y, a0.z, a0.w, a1.x, a1.y, a1.z, a1.w};
            float b[8] = {b0.x, b0.y, b0.z, b0.w, b1.x, b1.y, b1.z, b1.w};
#pragma unroll
            for (int i = 0; i < 8; i++)
#pragma unroll
                for (int j = 0; j < 8; j++) acc[i][j] += a[i] * b[j];
        }
        __syncthreads();
    }

#pragma unroll
    for (int i = 0; i < 8; i++) {
        int rg = m0 + ((i < 4) ? (ty * 4 + i) : (64 + ty * 4 + i - 4));
        float4 c0 = make_float4(acc[i][0], acc[i][1], acc[i][2], acc[i][3]);
        float4 c1 = make_float4(acc[i][4], acc[i][5], acc[i][6], acc[i][7]);
        *(float4*)(C + (size_t)rg * N + n0 + tx * 4) = c0;
        *(float4*)(C + (size_t)rg * N + n0 + 64 + tx * 4) = c1;
    }
}

// ---------------------------------------------------------------------------
// Flash attention (causal), fp32, register-blocked GEMM style.
// grid: (T/128, B*H). block: 256 threads, 2 CTAs/SM.
// Tile: BQ=128 q rows x BKV=64 kv cols. Thread (tx=tid%16, ty=tid/16) owns
// S[8][4]: rows ty*8..+7, cols tx*4..+3, and O[8][4] (same mapping, dims=cols).
// smem (dynamic, 100 KB): Qt[64][132] (Q^T), Kt[64][68] (K^T),
//                         Vs[64][68], Pt[64][132] (P^T).
// Inner loops: 3 LDS.128 per 32 FMA -> FMA-bound.
// ---------------------------------------------------------------------------
#define ATTN_SMEM ((64 * 132 + 64 * 68 + 64 * 68 + 64 * 132) * sizeof(float))

__global__ __launch_bounds__(256, 2) void attn_kernel()
{
    extern __shared__ float sm[];
    float (*Qt)[132] = (float(*)[132])(sm);
    float (*Kt)[68]  = (float(*)[68])(sm + 64 * 132);
    float (*Vs)[68]  = (float(*)[68])(sm + 64 * 132 + 64 * 68);
    float (*Pt)[132] = (float(*)[132])(sm + 64 * 132 + 2 * 64 * 68);

    const int tid = threadIdx.x;
    const int tx = tid & 15;
    const int ty = tid >> 4;
    const int qt = blockIdx.x;
    const int bh = blockIdx.y;
    const int b = bh >> 4;
    const int h = bh & 15;

    const float* base = g_qkv + (size_t)b * T_ * (3 * D_) + h * HD_;

    // Load Q^T: Qt[d][r] for r in [0,128), d in [0,64)
    for (int s = tid; s < 128 * 16; s += 256) {
        int r = s >> 4;
        int d4 = (s & 15) * 4;
        float4 v = *(const float4*)(base + (size_t)(qt * 128 + r) * (3 * D_) + d4);
        Qt[d4 + 0][r] = v.x; Qt[d4 + 1][r] = v.y;
        Qt[d4 + 2][r] = v.z; Qt[d4 + 3][r] = v.w;
    }

    float m[8], l[8], o[8][4];
#pragma unroll
    for (int i = 0; i < 8; i++) {
        m[i] = -1e30f; l[i] = 0.f;
#pragma unroll
        for (int jj = 0; jj < 4; jj++) o[i][jj] = 0.f;
    }

    const int jmax = 2 * qt + 1;
    for (int j0 = 0; j0 <= jmax; j0++) {
        __syncthreads();
        // Load K^T and V tiles [64 x 64]
        for (int s = tid; s < 64 * 16; s += 256) {
            int r = s >> 4;
            int d4 = (s & 15) * 4;
            const float* kp = base + D_ + (size_t)(j0 * 64 + r) * (3 * D_) + d4;
            float4 kv = *(const float4*)kp;
            float4 vv = *(const float4*)(kp + D_);
            Kt[d4 + 0][r] = kv.x; Kt[d4 + 1][r] = kv.y;
            Kt[d4 + 2][r] = kv.z; Kt[d4 + 3][r] = kv.w;
            *(float4*)&Vs[r][d4] = vv;
        }
        __syncthreads();

        // ---- S = Q K^T (8x4 per thread) ----
        float sacc[8][4];
#pragma unroll
        for (int i = 0; i < 8; i++)
#pragma unroll
            for (int jj = 0; jj < 4; jj++) sacc[i][jj] = 0.f;

#pragma unroll 8
        for (int d = 0; d < 64; d++) {
            float4 a0 = *(const float4*)&Qt[d][ty * 8];
            float4 a1 = *(const float4*)&Qt[d][ty * 8 + 4];
            float4 bq = *(const float4*)&Kt[d][tx * 4];
            float a[8] = {a0.x, a0.y, a0.z, a0.w, a1.x, a1.y, a1.z, a1.w};
            float bb[4] = {bq.x, bq.y, bq.z, bq.w};
#pragma unroll
            for (int i = 0; i < 8; i++)
#pragma unroll
                for (int jj = 0; jj < 4; jj++) sacc[i][jj] += a[i] * bb[jj];
        }

        // ---- softmax update ----
        const bool need_mask = (j0 >= 2 * qt);
#pragma unroll
        for (int i = 0; i < 8; i++) {
            const int qrow = qt * 128 + ty * 8 + i;
            float mx = -1e30f;
#pragma unroll
            for (int jj = 0; jj < 4; jj++) {
                float v = sacc[i][jj] * 0.125f;
                if (need_mask && (j0 * 64 + tx * 4 + jj > qrow)) v = -1e30f;
                sacc[i][jj] = v;
                mx = fmaxf(mx, v);
            }
            // reduce max across the 16 tx lanes (lane bits 0..3)
            mx = fmaxf(mx, __shfl_xor_sync(0xffffffffu, mx, 1));
            mx = fmaxf(mx, __shfl_xor_sync(0xffffffffu, mx, 2));
            mx = fmaxf(mx, __shfl_xor_sync(0xffffffffu, mx, 4));
            mx = fmaxf(mx, __shfl_xor_sync(0xffffffffu, mx, 8));
            float mnew = fmaxf(m[i], mx);
            float corr = __expf(m[i] - mnew);
            m[i] = mnew;

            float ls = 0.f;
#pragma unroll
            for (int jj = 0; jj < 4; jj++) {
                float p = __expf(sacc[i][jj] - mnew);
                sacc[i][jj] = p;
                Pt[tx * 4 + jj][ty * 8 + i] = p;
                ls += p;
            }
            ls += __shfl_xor_sync(0xffffffffu, ls, 1);
            ls += __shfl_xor_sync(0xffffffffu, ls, 2);
            ls += __shfl_xor_sync(0xffffffffu, ls, 4);
            ls += __shfl_xor_sync(0xffffffffu, ls, 8);
            l[i] = l[i] * corr + ls;
#pragma unroll
            for (int jj = 0; jj < 4; jj++) o[i][jj] *= corr;
        }

        // P a-frags for this thread are written only by threads of the same
        // warp (same ty group) -> warp-level sync suffices.
        __syncwarp();

        // ---- O += P V (8x4 per thread) ----
#pragma unroll 8
        for (int c = 0; c < 64; c++) {
            float4 a0 = *(const float4*)&Pt[c][ty * 8];
            float4 a1 = *(const float4*)&Pt[c][ty * 8 + 4];
            float4 bv = *(const float4*)&Vs[c][tx * 4];
            float a[8] = {a0.x, a0.y, a0.z, a0.w, a1.x, a1.y, a1.z, a1.w};
            float bb[4] = {bv.x, bv.y, bv.z, bv.w};
#pragma unroll
            for (int i = 0; i < 8; i++)
#pragma unroll
                for (int jj = 0; jj < 4; jj++) o[i][jj] += a[i] * bb[jj];
        }
    }

    // Epilogue: y[b, qt*128+ty*8+i, h*64 + tx*4 + jj] = o/l
#pragma unroll
    for (int i = 0; i < 8; i++) {
        float inv = 1.f / l[i];
        float* yp = g_y + ((size_t)b * T_ + qt * 128 + ty * 8 + i) * D_ + h * HD_ + tx * 4;
        float4 v = make_float4(o[i][0] * inv, o[i][1] * inv,
                               o[i][2] * inv, o[i][3] * inv);
        *(float4*)yp = v;
    }
}

// ---------------------------------------------------------------------------
extern "C" void kernel_launch(void* const* d_in, const int* in_sizes, int n_in,
                              void* d_out, int out_size)
{
    const float* x      = (const float*)d_in[0];
    const float* w_qkv  = (const float*)d_in[1];
    const float* w_proj = (const float*)d_in[2];
    float* out = (float*)d_out;

    // QKV GEMM: [4096,1024] @ [3072,1024]^T -> g_qkv [4096,3072]
    {
        dim3 grid(3 * D_ / 128, M_ROWS / 128);
        sgemm_nt_kernel<M_ROWS, 3 * D_, D_, true, false><<<grid, 256>>>(x, w_qkv, nullptr);
    }

    // Attention -> g_y
    {
        static bool attr_set = false;
        if (!attr_set) {
            cudaFuncSetAttribute(attn_kernel, cudaFuncAttributeMaxDynamicSharedMemorySize,
                                 (int)ATTN_SMEM);
            attr_set = true;
        }
        dim3 grid(T_ / 128, B_ * H_);
        attn_kernel<<<grid, 256, ATTN_SMEM>>>();
    }

    // Proj GEMM: g_y [4096,1024] @ [1024,1024]^T -> out
    {
        dim3 grid(D_ / 128, M_ROWS / 128);
        sgemm_nt_kernel<M_ROWS, D_, D_, false, true><<<grid, 256>>>(nullptr, w_proj, out);
    }
}

// round 5
// speedup vs baseline: 2.6383x; 1.4453x over previous
#include <cuda_runtime.h>
#include <cuda_fp16.h>
#include <cstdint>

// Problem constants
#define B_  2
#define T_  2048
#define D_  1024
#define H_  16
#define HD_ 64
#define M_ROWS (B_ * T_)   // 4096

// ---------------------------------------------------------------------------
// Scratch (allocation-free rule: __device__ globals)
// ---------------------------------------------------------------------------
__device__ float  g_qkv[(size_t)B_ * T_ * 3 * D_];     // [B,T,3D] fp32
__device__ __half g_xhi[(size_t)M_ROWS * D_];
__device__ __half g_xlo[(size_t)M_ROWS * D_];
__device__ __half g_wqkvhi[(size_t)3 * D_ * D_];
__device__ __half g_wqkvlo[(size_t)3 * D_ * D_];
__device__ __half g_wphi[(size_t)D_ * D_];
__device__ __half g_wplo[(size_t)D_ * D_];
__device__ __half g_yhi[(size_t)M_ROWS * D_];
__device__ __half g_ylo[(size_t)M_ROWS * D_];

// ---------------------------------------------------------------------------
// Helpers (baseline PTX only: ldmatrix, mma.sync, cp.async — no 'a' features)
// ---------------------------------------------------------------------------
__device__ __forceinline__ uint32_t smem_u32(const void* p) {
    uint32_t a;
    asm("{ .reg .u64 t; cvta.to.shared.u64 t, %1; cvt.u32.u64 %0, t; }" : "=r"(a) : "l"(p));
    return a;
}

#define CP_ASYNC16(dst, src) \
    asm volatile("cp.async.cg.shared.global [%0], [%1], 16;" :: "r"(dst), "l"(src) : "memory")
#define CP_COMMIT() asm volatile("cp.async.commit_group;" ::: "memory")
#define CP_WAIT1()  asm volatile("cp.async.wait_group 1;" ::: "memory")
#define CP_WAIT0()  asm volatile("cp.async.wait_group 0;" ::: "memory")

#define LDSM_X4(r0, r1, r2, r3, addr)                                          \
    asm volatile("ldmatrix.sync.aligned.m8n8.x4.shared.b16 {%0,%1,%2,%3}, [%4];" \
                 : "=r"(r0), "=r"(r1), "=r"(r2), "=r"(r3) : "r"(addr))

#define MMA16816(c, a0, a1, a2, a3, b0, b1)                                    \
    asm volatile("mma.sync.aligned.m16n8k16.row.col.f32.f16.f16.f32 "          \
                 "{%0,%1,%2,%3}, {%4,%5,%6,%7}, {%8,%9}, {%0,%1,%2,%3};"       \
                 : "+f"((c)[0]), "+f"((c)[1]), "+f"((c)[2]), "+f"((c)[3])      \
                 : "r"(a0), "r"(a1), "r"(a2), "r"(a3), "r"(b0), "r"(b1))

// ---------------------------------------------------------------------------
// Split kernel: fp32 -> (hi, lo) fp16 where hi = fp16(x), lo = fp16(x - hi)
// ---------------------------------------------------------------------------
__global__ void split_kernel(const float* __restrict__ in, __half* __restrict__ hi,
                             __half* __restrict__ lo, int n4) {
    int i = blockIdx.x * blockDim.x + threadIdx.x;
    if (i >= n4) return;
    float4 v = ((const float4*)in)[i];
    float f[4] = {v.x, v.y, v.z, v.w};
    __half h[4], l[4];
#pragma unroll
    for (int j = 0; j < 4; j++) {
        h[j] = __float2half_rn(f[j]);
        l[j] = __float2half_rn(f[j] - __half2float(h[j]));
    }
    ((__half2*)hi)[i * 2 + 0] = __halves2half2(h[0], h[1]);
    ((__half2*)hi)[i * 2 + 1] = __halves2half2(h[2], h[3]);
    ((__half2*)lo)[i * 2 + 0] = __halves2half2(l[0], l[1]);
    ((__half2*)lo)[i * 2 + 1] = __halves2half2(l[2], l[3]);
}

// ---------------------------------------------------------------------------
// HMMA fp16-split GEMM: C[M,N] = (Ahi+Alo)[M,K] @ (Bhi+Blo)[N,K]^T
// 3 passes (hi*hi + hi*lo + lo*hi), fp32 acc, mma.sync m16n8k16.
// CTA 128x128, 8 warps (4M x 2N), warp 32x64. BK=32, double-buffered cp.async.
// smem rows padded to 40 halves (80B) -> conflict-free ldmatrix.
// ---------------------------------------------------------------------------
#define GLDS 40                   // halves per smem row
#define GAS  (128 * GLDS)         // halves per array
#define GSTG (4 * GAS)            // halves per stage (Ahi,Alo,Bhi,Blo)
#define GK_SMEM (2 * GSTG * (int)sizeof(__half))

template <int N_, int K_>
__global__ __launch_bounds__(256, 2) void hmma_gemm(
    const __half* __restrict__ Ahi, const __half* __restrict__ Alo,
    const __half* __restrict__ Bhi, const __half* __restrict__ Blo,
    float* __restrict__ C)
{
    extern __shared__ __half sh[];
    const int tid = threadIdx.x;
    const int lane = tid & 31;
    const int wid = tid >> 5;
    const int wm = wid >> 1;          // 0..3
    const int wn = wid & 1;           // 0..1
    const int m0 = blockIdx.y * 128;
    const int n0 = blockIdx.x * 128;

    float acc[2][8][4];
#pragma unroll
    for (int mt = 0; mt < 2; mt++)
#pragma unroll
        for (int nt = 0; nt < 8; nt++)
#pragma unroll
            for (int q = 0; q < 4; q++) acc[mt][nt][q] = 0.f;

    const __half* gsrc[4] = {Ahi, Alo, Bhi, Blo};

    auto stage_load = [&](int s, int kt) {
        __half* base = sh + s * GSTG;
#pragma unroll
        for (int arr = 0; arr < 4; arr++) {
            const __half* g = gsrc[arr];
            const int row0 = (arr < 2) ? m0 : n0;
#pragma unroll
            for (int i = 0; i < 2; i++) {
                int c = tid + i * 256;
                int row = c >> 2, seg = c & 3;
                uint32_t dst = smem_u32(base + arr * GAS + row * GLDS + seg * 8);
                const __half* src = g + (size_t)(row0 + row) * K_ + kt * 32 + seg * 8;
                CP_ASYNC16(dst, src);
            }
        }
    };

    // ldmatrix lane addressing (constant per thread)
    const int a_row = (lane & 15);
    const int a_col = (lane >> 4) * 8;
    const int b_row = ((lane & 16) ? 8 : 0) + (lane & 7);
    const int b_col = ((lane & 8) ? 8 : 0);

    stage_load(0, 0);
    CP_COMMIT();

    constexpr int KT = K_ / 32;
    for (int kt = 0; kt < KT; kt++) {
        if (kt + 1 < KT) {
            stage_load((kt + 1) & 1, kt + 1);
            CP_COMMIT();
            CP_WAIT1();
        } else {
            CP_WAIT0();
        }
        __syncthreads();

        const __half* base = sh + (kt & 1) * GSTG;
        const uint32_t ah_b = smem_u32(base);
        const uint32_t al_b = smem_u32(base + GAS);
        const uint32_t bh_b = smem_u32(base + 2 * GAS);
        const uint32_t bl_b = smem_u32(base + 3 * GAS);

#pragma unroll
        for (int ks = 0; ks < 2; ks++) {
            const int k0 = ks * 16;
            uint32_t bh[4][4], bl[4][4];
#pragma unroll
            for (int p = 0; p < 4; p++) {
                const int nB = wn * 64 + p * 16;
                uint32_t off = (uint32_t)((nB + b_row) * GLDS + k0 + b_col) * 2;
                LDSM_X4(bh[p][0], bh[p][1], bh[p][2], bh[p][3], bh_b + off);
                LDSM_X4(bl[p][0], bl[p][1], bl[p][2], bl[p][3], bl_b + off);
            }
#pragma unroll
            for (int mt = 0; mt < 2; mt++) {
                const int rA = wm * 32 + mt * 16;
                uint32_t off = (uint32_t)((rA + a_row) * GLDS + k0 + a_col) * 2;
                uint32_t ah0, ah1, ah2, ah3, al0, al1, al2, al3;
                LDSM_X4(ah0, ah1, ah2, ah3, ah_b + off);
                LDSM_X4(al0, al1, al2, al3, al_b + off);
#pragma unroll
                for (int p = 0; p < 4; p++) {
#pragma unroll
                    for (int t = 0; t < 2; t++) {
                        const int nt = p * 2 + t;
                        uint32_t b0h = bh[p][t * 2], b1h = bh[p][t * 2 + 1];
                        uint32_t b0l = bl[p][t * 2], b1l = bl[p][t * 2 + 1];
                        MMA16816(acc[mt][nt], ah0, ah1, ah2, ah3, b0h, b1h);
                        MMA16816(acc[mt][nt], ah0, ah1, ah2, ah3, b0l, b1l);
                        MMA16816(acc[mt][nt], al0, al1, al2, al3, b0h, b1h);
                    }
                }
            }
        }
        __syncthreads();
    }

    // Epilogue: c0,c1 -> (row, col..col+1); c2,c3 -> (row+8, ...)
#pragma unroll
    for (int mt = 0; mt < 2; mt++) {
#pragma unroll
        for (int nt = 0; nt < 8; nt++) {
            const int row = m0 + wm * 32 + mt * 16 + (lane >> 2);
            const int col = n0 + wn * 64 + nt * 8 + 2 * (lane & 3);
            *(float2*)(C + (size_t)row * N_ + col) =
                make_float2(acc[mt][nt][0], acc[mt][nt][1]);
            *(float2*)(C + (size_t)(row + 8) * N_ + col) =
                make_float2(acc[mt][nt][2], acc[mt][nt][3]);
        }
    }
}

// ---------------------------------------------------------------------------
// Flash attention (causal), fp32, register-blocked (proven at ~650us).
// Epilogue writes y as fp16 (hi, lo) for the HMMA proj GEMM.
// ---------------------------------------------------------------------------
#define ATTN_SMEM ((64 * 132 + 64 * 68 + 64 * 68 + 64 * 132) * sizeof(float))

__global__ __launch_bounds__(256, 2) void attn_kernel()
{
    extern __shared__ float sm[];
    float (*Qt)[132] = (float(*)[132])(sm);
    float (*Kt)[68]  = (float(*)[68])(sm + 64 * 132);
    float (*Vs)[68]  = (float(*)[68])(sm + 64 * 132 + 64 * 68);
    float (*Pt)[132] = (float(*)[132])(sm + 64 * 132 + 2 * 64 * 68);

    const int tid = threadIdx.x;
    const int tx = tid & 15;
    const int ty = tid >> 4;
    const int qt = blockIdx.x;
    const int bh = blockIdx.y;
    const int b = bh >> 4;
    const int h = bh & 15;

    const float* base = g_qkv + (size_t)b * T_ * (3 * D_) + h * HD_;

    for (int s = tid; s < 128 * 16; s += 256) {
        int r = s >> 4;
        int d4 = (s & 15) * 4;
        float4 v = *(const float4*)(base + (size_t)(qt * 128 + r) * (3 * D_) + d4);
        Qt[d4 + 0][r] = v.x; Qt[d4 + 1][r] = v.y;
        Qt[d4 + 2][r] = v.z; Qt[d4 + 3][r] = v.w;
    }

    float m[8], l[8], o[8][4];
#pragma unroll
    for (int i = 0; i < 8; i++) {
        m[i] = -1e30f; l[i] = 0.f;
#pragma unroll
        for (int jj = 0; jj < 4; jj++) o[i][jj] = 0.f;
    }

    const int jmax = 2 * qt + 1;
    for (int j0 = 0; j0 <= jmax; j0++) {
        __syncthreads();
        for (int s = tid; s < 64 * 16; s += 256) {
            int r = s >> 4;
            int d4 = (s & 15) * 4;
            const float* kp = base + D_ + (size_t)(j0 * 64 + r) * (3 * D_) + d4;
            float4 kv = *(const float4*)kp;
            float4 vv = *(const float4*)(kp + D_);
            Kt[d4 + 0][r] = kv.x; Kt[d4 + 1][r] = kv.y;
            Kt[d4 + 2][r] = kv.z; Kt[d4 + 3][r] = kv.w;
            *(float4*)&Vs[r][d4] = vv;
        }
        __syncthreads();

        float sacc[8][4];
#pragma unroll
        for (int i = 0; i < 8; i++)
#pragma unroll
            for (int jj = 0; jj < 4; jj++) sacc[i][jj] = 0.f;

#pragma unroll 8
        for (int d = 0; d < 64; d++) {
            float4 a0 = *(const float4*)&Qt[d][ty * 8];
            float4 a1 = *(const float4*)&Qt[d][ty * 8 + 4];
            float4 bq = *(const float4*)&Kt[d][tx * 4];
            float a[8] = {a0.x, a0.y, a0.z, a0.w, a1.x, a1.y, a1.z, a1.w};
            float bb[4] = {bq.x, bq.y, bq.z, bq.w};
#pragma unroll
            for (int i = 0; i < 8; i++)
#pragma unroll
                for (int jj = 0; jj < 4; jj++) sacc[i][jj] += a[i] * bb[jj];
        }

        const bool need_mask = (j0 >= 2 * qt);
#pragma unroll
        for (int i = 0; i < 8; i++) {
            const int qrow = qt * 128 + ty * 8 + i;
            float mx = -1e30f;
#pragma unroll
            for (int jj = 0; jj < 4; jj++) {
                float v = sacc[i][jj] * 0.125f;
                if (need_mask && (j0 * 64 + tx * 4 + jj > qrow)) v = -1e30f;
                sacc[i][jj] = v;
                mx = fmaxf(mx, v);
            }
            mx = fmaxf(mx, __shfl_xor_sync(0xffffffffu, mx, 1));
            mx = fmaxf(mx, __shfl_xor_sync(0xffffffffu, mx, 2));
            mx = fmaxf(mx, __shfl_xor_sync(0xffffffffu, mx, 4));
            mx = fmaxf(mx, __shfl_xor_sync(0xffffffffu, mx, 8));
            float mnew = fmaxf(m[i], mx);
            float corr = __expf(m[i] - mnew);
            m[i] = mnew;

            float ls = 0.f;
#pragma unroll
            for (int jj = 0; jj < 4; jj++) {
                float p = __expf(sacc[i][jj] - mnew);
                sacc[i][jj] = p;
                Pt[tx * 4 + jj][ty * 8 + i] = p;
                ls += p;
            }
            ls += __shfl_xor_sync(0xffffffffu, ls, 1);
            ls += __shfl_xor_sync(0xffffffffu, ls, 2);
            ls += __shfl_xor_sync(0xffffffffu, ls, 4);
            ls += __shfl_xor_sync(0xffffffffu, ls, 8);
            l[i] = l[i] * corr + ls;
#pragma unroll
            for (int jj = 0; jj < 4; jj++) o[i][jj] *= corr;
        }

        __syncwarp();

#pragma unroll 8
        for (int c = 0; c < 64; c++) {
            float4 a0 = *(const float4*)&Pt[c][ty * 8];
            float4 a1 = *(const float4*)&Pt[c][ty * 8 + 4];
            float4 bv = *(const float4*)&Vs[c][tx * 4];
            float a[8] = {a0.x, a0.y, a0.z, a0.w, a1.x, a1.y, a1.z, a1.w};
            float bb[4] = {bv.x, bv.y, bv.z, bv.w};
#pragma unroll
            for (int i = 0; i < 8; i++)
#pragma unroll
                for (int jj = 0; jj < 4; jj++) o[i][jj] += a[i] * bb[jj];
        }
    }

    // Epilogue: y -> (hi, lo) fp16
#pragma unroll
    for (int i = 0; i < 8; i++) {
        float inv = 1.f / l[i];
        size_t idx = ((size_t)b * T_ + qt * 128 + ty * 8 + i) * D_ + h * HD_ + tx * 4;
        __half h0[4], l0[4];
#pragma unroll
        for (int jj = 0; jj < 4; jj++) {
            float v = o[i][jj] * inv;
            h0[jj] = __float2half_rn(v);
            l0[jj] = __float2half_rn(v - __half2float(h0[jj]));
        }
        *(__half2*)(g_yhi + idx)     = __halves2half2(h0[0], h0[1]);
        *(__half2*)(g_yhi + idx + 2) = __halves2half2(h0[2], h0[3]);
        *(__half2*)(g_ylo + idx)     = __halves2half2(l0[0], l0[1]);
        *(__half2*)(g_ylo + idx + 2) = __halves2half2(l0[2], l0[3]);
    }
}

// ---------------------------------------------------------------------------
extern "C" void kernel_launch(void* const* d_in, const int* in_sizes, int n_in,
                              void* d_out, int out_size)
{
    const float* x      = (const float*)d_in[0];
    const float* w_qkv  = (const float*)d_in[1];
    const float* w_proj = (const float*)d_in[2];
    float* out = (float*)d_out;

    static bool attr_set = false;
    if (!attr_set) {
        cudaFuncSetAttribute(attn_kernel, cudaFuncAttributeMaxDynamicSharedMemorySize,
                             (int)ATTN_SMEM);
        cudaFuncSetAttribute(hmma_gemm<3 * D_, D_>,
                             cudaFuncAttributeMaxDynamicSharedMemorySize, GK_SMEM);
        cudaFuncSetAttribute(hmma_gemm<D_, D_>,
                             cudaFuncAttributeMaxDynamicSharedMemorySize, GK_SMEM);
        attr_set = true;
    }

    __half *xhi, *xlo, *wqh, *wql, *wph, *wpl, *yhi, *ylo;
    float* qkv;
    cudaGetSymbolAddress((void**)&xhi, g_xhi);
    cudaGetSymbolAddress((void**)&xlo, g_xlo);
    cudaGetSymbolAddress((void**)&wqh, g_wqkvhi);
    cudaGetSymbolAddress((void**)&wql, g_wqkvlo);
    cudaGetSymbolAddress((void**)&wph, g_wphi);
    cudaGetSymbolAddress((void**)&wpl, g_wplo);
    cudaGetSymbolAddress((void**)&yhi, g_yhi);
    cudaGetSymbolAddress((void**)&ylo, g_ylo);
    cudaGetSymbolAddress((void**)&qkv, g_qkv);

    // Split inputs to fp16 hi/lo
    {
        int n4 = M_ROWS * D_ / 4;
        split_kernel<<<(n4 + 255) / 256, 256>>>(x, xhi, xlo, n4);
        n4 = 3 * D_ * D_ / 4;
        split_kernel<<<(n4 + 255) / 256, 256>>>(w_qkv, wqh, wql, n4);
        n4 = D_ * D_ / 4;
        split_kernel<<<(n4 + 255) / 256, 256>>>(w_proj, wph, wpl, n4);
    }

    // QKV GEMM (HMMA): [4096,1024] @ [3072,1024]^T -> g_qkv fp32
    {
        dim3 grid(3 * D_ / 128, M_ROWS / 128);
        hmma_gemm<3 * D_, D_><<<grid, 256, GK_SMEM>>>(xhi, xlo, wqh, wql, qkv);
    }

    // Attention -> y (fp16 hi/lo)
    {
        dim3 grid(T_ / 128, B_ * H_);
        attn_kernel<<<grid, 256, ATTN_SMEM>>>();
    }

    // Proj GEMM (HMMA): y [4096,1024] @ [1024,1024]^T -> out fp32
    {
        dim3 grid(D_ / 128, M_ROWS / 128);
        hmma_gemm<D_, D_><<<grid, 256, GK_SMEM>>>(yhi, ylo, wph, wpl, out);
    }
}

// round 7
// speedup vs baseline: 4.0469x; 1.5339x over previous
#include <cuda_runtime.h>
#include <cuda_fp16.h>
#include <cstdint>

// Problem constants
#define B_  2
#define T_  2048
#define D_  1024
#define H_  16
#define HD_ 64
#define M_ROWS (B_ * T_)   // 4096

// ---------------------------------------------------------------------------
// Scratch (allocation-free rule: __device__ globals)
// ---------------------------------------------------------------------------
__device__ __half g_xhi[(size_t)M_ROWS * D_];
__device__ __half g_xlo[(size_t)M_ROWS * D_];
__device__ __half g_wqkvhi[(size_t)3 * D_ * D_];
__device__ __half g_wqkvlo[(size_t)3 * D_ * D_];
__device__ __half g_wphi[(size_t)D_ * D_];
__device__ __half g_wplo[(size_t)D_ * D_];
__device__ __half g_qkvhi[(size_t)M_ROWS * 3 * D_];
__device__ __half g_qkvlo[(size_t)M_ROWS * 3 * D_];
__device__ __half g_yhi[(size_t)M_ROWS * D_];
__device__ __half g_ylo[(size_t)M_ROWS * D_];

// ---------------------------------------------------------------------------
// Helpers (baseline PTX only)
// ---------------------------------------------------------------------------
__device__ __forceinline__ uint32_t smem_u32(const void* p) {
    uint32_t a;
    asm("{ .reg .u64 t; cvta.to.shared.u64 t, %1; cvt.u32.u64 %0, t; }" : "=r"(a) : "l"(p));
    return a;
}

#define CP_ASYNC16(dst, src) \
    asm volatile("cp.async.cg.shared.global [%0], [%1], 16;" :: "r"(dst), "l"(src) : "memory")
#define CP_COMMIT() asm volatile("cp.async.commit_group;" ::: "memory")
#define CP_WAIT1()  asm volatile("cp.async.wait_group 1;" ::: "memory")
#define CP_WAIT0()  asm volatile("cp.async.wait_group 0;" ::: "memory")

#define LDSM_X4(r0, r1, r2, r3, addr)                                          \
    asm volatile("ldmatrix.sync.aligned.m8n8.x4.shared.b16 {%0,%1,%2,%3}, [%4];" \
                 : "=r"(r0), "=r"(r1), "=r"(r2), "=r"(r3) : "r"(addr))

#define MMA16816(c, a0, a1, a2, a3, b0, b1)                                    \
    asm volatile("mma.sync.aligned.m16n8k16.row.col.f32.f16.f16.f32 "          \
                 "{%0,%1,%2,%3}, {%4,%5,%6,%7}, {%8,%9}, {%0,%1,%2,%3};"       \
                 : "+f"((c)[0]), "+f"((c)[1]), "+f"((c)[2]), "+f"((c)[3])      \
                 : "r"(a0), "r"(a1), "r"(a2), "r"(a3), "r"(b0), "r"(b1))

__device__ __forceinline__ uint32_t f2h2(float a, float b) {
    __half2 t = __floats2half2_rn(a, b);
    return *reinterpret_cast<uint32_t*>(&t);
}
__device__ __forceinline__ uint32_t f2h2_lo(float a, float b, uint32_t hi) {
    __half2 h = *reinterpret_cast<__half2*>(&hi);
    __half2 t = __floats2half2_rn(a - __low2float(h), b - __high2float(h));
    return *reinterpret_cast<uint32_t*>(&t);
}

// ---------------------------------------------------------------------------
// Split kernel: fp32 -> (hi, lo) fp16
// ---------------------------------------------------------------------------
__global__ void split_kernel(const float* __restrict__ in, __half* __restrict__ hi,
                             __half* __restrict__ lo, int n4) {
    int i = blockIdx.x * blockDim.x + threadIdx.x;
    if (i >= n4) return;
    float4 v = ((const float4*)in)[i];
    float f[4] = {v.x, v.y, v.z, v.w};
    __half h[4], l[4];
#pragma unroll
    for (int j = 0; j < 4; j++) {
        h[j] = __float2half_rn(f[j]);
        l[j] = __float2half_rn(f[j] - __half2float(h[j]));
    }
    ((__half2*)hi)[i * 2 + 0] = __halves2half2(h[0], h[1]);
    ((__half2*)hi)[i * 2 + 1] = __halves2half2(h[2], h[3]);
    ((__half2*)lo)[i * 2 + 0] = __halves2half2(l[0], l[1]);
    ((__half2*)lo)[i * 2 + 1] = __halves2half2(l[2], l[3]);
}

// ---------------------------------------------------------------------------
// HMMA fp16-split GEMM (3 passes). OUT_SPLIT=1 -> write hi/lo halves.
// ---------------------------------------------------------------------------
#define GLDS 40
#define GAS  (128 * GLDS)
#define GSTG (4 * GAS)
#define GK_SMEM (2 * GSTG * (int)sizeof(__half))

template <int N_, int K_, int OUT_SPLIT>
__global__ __launch_bounds__(256, 2) void hmma_gemm(
    const __half* __restrict__ Ahi, const __half* __restrict__ Alo,
    const __half* __restrict__ Bhi, const __half* __restrict__ Blo,
    float* __restrict__ C, __half* __restrict__ Chi, __half* __restrict__ Clo)
{
    extern __shared__ __half sh[];
    const int tid = threadIdx.x;
    const int lane = tid & 31;
    const int wid = tid >> 5;
    const int wm = wid >> 1;
    const int wn = wid & 1;
    const int m0 = blockIdx.y * 128;
    const int n0 = blockIdx.x * 128;

    float acc[2][8][4];
#pragma unroll
    for (int mt = 0; mt < 2; mt++)
#pragma unroll
        for (int nt = 0; nt < 8; nt++)
#pragma unroll
            for (int q = 0; q < 4; q++) acc[mt][nt][q] = 0.f;

    const __half* gsrc[4] = {Ahi, Alo, Bhi, Blo};

    auto stage_load = [&](int s, int kt) {
        __half* base = sh + s * GSTG;
#pragma unroll
        for (int arr = 0; arr < 4; arr++) {
            const __half* g = gsrc[arr];
            const int row0 = (arr < 2) ? m0 : n0;
#pragma unroll
            for (int i = 0; i < 2; i++) {
                int c = tid + i * 256;
                int row = c >> 2, seg = c & 3;
                uint32_t dst = smem_u32(base + arr * GAS + row * GLDS + seg * 8);
                const __half* src = g + (size_t)(row0 + row) * K_ + kt * 32 + seg * 8;
                CP_ASYNC16(dst, src);
            }
        }
    };

    const int a_row = (lane & 15);
    const int a_col = (lane >> 4) * 8;
    const int b_row = ((lane & 16) ? 8 : 0) + (lane & 7);
    const int b_col = ((lane & 8) ? 8 : 0);

    stage_load(0, 0);
    CP_COMMIT();

    constexpr int KT = K_ / 32;
    for (int kt = 0; kt < KT; kt++) {
        if (kt + 1 < KT) {
            stage_load((kt + 1) & 1, kt + 1);
            CP_COMMIT();
            CP_WAIT1();
        } else {
            CP_WAIT0();
        }
        __syncthreads();

        const __half* base = sh + (kt & 1) * GSTG;
        const uint32_t ah_b = smem_u32(base);
        const uint32_t al_b = smem_u32(base + GAS);
        const uint32_t bh_b = smem_u32(base + 2 * GAS);
        const uint32_t bl_b = smem_u32(base + 3 * GAS);

#pragma unroll
        for (int ks = 0; ks < 2; ks++) {
            const int k0 = ks * 16;
            uint32_t bh[4][4], bl[4][4];
#pragma unroll
            for (int p = 0; p < 4; p++) {
                const int nB = wn * 64 + p * 16;
                uint32_t off = (uint32_t)((nB + b_row) * GLDS + k0 + b_col) * 2;
                LDSM_X4(bh[p][0], bh[p][1], bh[p][2], bh[p][3], bh_b + off);
                LDSM_X4(bl[p][0], bl[p][1], bl[p][2], bl[p][3], bl_b + off);
            }
#pragma unroll
            for (int mt = 0; mt < 2; mt++) {
                const int rA = wm * 32 + mt * 16;
                uint32_t off = (uint32_t)((rA + a_row) * GLDS + k0 + a_col) * 2;
                uint32_t ah0, ah1, ah2, ah3, al0, al1, al2, al3;
                LDSM_X4(ah0, ah1, ah2, ah3, ah_b + off);
                LDSM_X4(al0, al1, al2, al3, al_b + off);
#pragma unroll
                for (int p = 0; p < 4; p++) {
#pragma unroll
                    for (int t = 0; t < 2; t++) {
                        const int nt = p * 2 + t;
                        MMA16816(acc[mt][nt], ah0, ah1, ah2, ah3, bh[p][t * 2], bh[p][t * 2 + 1]);
                        MMA16816(acc[mt][nt], ah0, ah1, ah2, ah3, bl[p][t * 2], bl[p][t * 2 + 1]);
                        MMA16816(acc[mt][nt], al0, al1, al2, al3, bh[p][t * 2], bh[p][t * 2 + 1]);
                    }
                }
            }
        }
        __syncthreads();
    }

#pragma unroll
    for (int mt = 0; mt < 2; mt++) {
#pragma unroll
        for (int nt = 0; nt < 8; nt++) {
            const int row = m0 + wm * 32 + mt * 16 + (lane >> 2);
            const int col = n0 + wn * 64 + nt * 8 + 2 * (lane & 3);
#pragma unroll
            for (int rr = 0; rr < 2; rr++) {
                float c0 = acc[mt][nt][rr * 2], c1 = acc[mt][nt][rr * 2 + 1];
                size_t idx = (size_t)(row + rr * 8) * N_ + col;
                if (OUT_SPLIT) {
                    uint32_t hi = f2h2(c0, c1);
                    uint32_t lo = f2h2_lo(c0, c1, hi);
                    *(uint32_t*)(Chi + idx) = hi;
                    *(uint32_t*)(Clo + idx) = lo;
                } else {
                    *(float2*)(C + idx) = make_float2(c0, c1);
                }
            }
        }
    }
}

// ---------------------------------------------------------------------------
// HMMA flash attention (causal). CTA: 128 q-rows x one (b,h); BKV=64.
// 8 warps, each 16 rows x 64 cols. S = QK^T 3-pass split; softmax in C-frag
// layout (quad shfl); P->A frags in registers; PV 3-pass with V^T in smem.
// smem stride 72 halves (144B) -> conflict-free ldmatrix row pointers.
// ---------------------------------------------------------------------------
#define AST 72
#define ATTN_SMEM ((2 * 128 + 4 * 64) * AST * (int)sizeof(__half))  // 73728 B

__global__ __launch_bounds__(256, 1) void attn_hmma()
{
    extern __shared__ __half sh[];
    __half* Qhi  = sh;
    __half* Qlo  = Qhi + 128 * AST;
    __half* Khi  = Qlo + 128 * AST;
    __half* Klo  = Khi + 64 * AST;
    __half* Vthi = Klo + 64 * AST;
    __half* Vtlo = Vthi + 64 * AST;

    const int tid = threadIdx.x;
    const int lane = tid & 31;
    const int wid = tid >> 5;
    const int qt = (int)gridDim.x - 1 - (int)blockIdx.x;   // heavy CTAs first
    const int bh = blockIdx.y;
    const int b = bh >> 4;
    const int h = bh & 15;

    const __half* ghi = g_qkvhi + (size_t)b * T_ * (3 * D_) + h * HD_;
    const __half* glo = g_qkvlo + (size_t)b * T_ * (3 * D_) + h * HD_;

    // Load Q (128 rows x 64 halves, hi+lo)
#pragma unroll
    for (int i = 0; i < 4; i++) {
        int c = tid + i * 256;
        int r = c >> 3, d8 = (c & 7) * 8;
        size_t g = (size_t)(qt * 128 + r) * (3 * D_) + d8;
        *(uint4*)&Qhi[r * AST + d8] = *(const uint4*)(ghi + g);
        *(uint4*)&Qlo[r * AST + d8] = *(const uint4*)(glo + g);
    }

    float o[8][4];
    float m[2] = {-1e30f, -1e30f}, l[2] = {0.f, 0.f};
#pragma unroll
    for (int nt = 0; nt < 8; nt++)
#pragma unroll
        for (int q = 0; q < 4; q++) o[nt][q] = 0.f;

    const int a_row = (lane & 15);
    const int a_col = (lane >> 4) * 8;
    const int b_row = ((lane & 16) ? 8 : 0) + (lane & 7);
    const int b_col = ((lane & 8) ? 8 : 0);

    const uint32_t qhi_b = smem_u32(Qhi), qlo_b = smem_u32(Qlo);
    const uint32_t khi_b = smem_u32(Khi), klo_b = smem_u32(Klo);
    const uint32_t vhi_b = smem_u32(Vthi), vlo_b = smem_u32(Vtlo);

    const int jmax = 2 * qt + 1;
    for (int j0 = 0; j0 <= jmax; j0++) {
        __syncthreads();
        // Load K (natural) and V (transposed to [d][kv]), hi+lo
#pragma unroll
        for (int i = 0; i < 2; i++) {
            int c = tid + i * 256;
            int r = c >> 3, d8 = (c & 7) * 8;
            size_t gk = (size_t)(j0 * 64 + r) * (3 * D_) + D_ + d8;
            *(uint4*)&Khi[r * AST + d8] = *(const uint4*)(ghi + gk);
            *(uint4*)&Klo[r * AST + d8] = *(const uint4*)(glo + gk);
            size_t gv = (size_t)(j0 * 64 + r) * (3 * D_) + 2 * D_ + d8;
            uint4 vh = *(const uint4*)(ghi + gv);
            uint4 vl = *(const uint4*)(glo + gv);
            const __half* ph = (const __half*)&vh;
            const __half* pl = (const __half*)&vl;
#pragma unroll
            for (int k = 0; k < 8; k++) {
                Vthi[(d8 + k) * AST + r] = ph[k];
                Vtlo[(d8 + k) * AST + r] = pl[k];
            }
        }
        __syncthreads();

        // ---- S = Q K^T (3-pass) ----
        float sacc[8][4];
#pragma unroll
        for (int nt = 0; nt < 8; nt++)
#pragma unroll
            for (int q = 0; q < 4; q++) sacc[nt][q] = 0.f;

#pragma unroll
        for (int ks = 0; ks < 4; ks++) {
            uint32_t offA = (uint32_t)((wid * 16 + a_row) * AST + ks * 16 + a_col) * 2;
            uint32_t ah0, ah1, ah2, ah3, al0, al1, al2, al3;
            LDSM_X4(ah0, ah1, ah2, ah3, qhi_b + offA);
            LDSM_X4(al0, al1, al2, al3, qlo_b + offA);
            uint32_t bhf[4][4], blf[4][4];
#pragma unroll
            for (int p = 0; p < 4; p++) {
                uint32_t offB = (uint32_t)((p * 16 + b_row) * AST + ks * 16 + b_col) * 2;
                LDSM_X4(bhf[p][0], bhf[p][1], bhf[p][2], bhf[p][3], khi_b + offB);
                LDSM_X4(blf[p][0], blf[p][1], blf[p][2], blf[p][3], klo_b + offB);
            }
#pragma unroll
            for (int p = 0; p < 4; p++)
#pragma unroll
                for (int t = 0; t < 2; t++) {
                    const int nt = p * 2 + t;
                    MMA16816(sacc[nt], ah0, ah1, ah2, ah3, bhf[p][t * 2], bhf[p][t * 2 + 1]);
                    MMA16816(sacc[nt], ah0, ah1, ah2, ah3, blf[p][t * 2], blf[p][t * 2 + 1]);
                    MMA16816(sacc[nt], al0, al1, al2, al3, bhf[p][t * 2], bhf[p][t * 2 + 1]);
                }
        }

        // ---- softmax (rows: lane>>2 and +8; cols spread over lane&3) ----
        const bool need_mask = (j0 >= 2 * qt);
#pragma unroll
        for (int hf = 0; hf < 2; hf++) {
            const int qrow = qt * 128 + wid * 16 + (lane >> 2) + hf * 8;
            float mx = -1e30f;
#pragma unroll
            for (int nt = 0; nt < 8; nt++)
#pragma unroll
                for (int u = 0; u < 2; u++) {
                    float v = sacc[nt][hf * 2 + u] * 0.125f;
                    if (need_mask && (j0 * 64 + nt * 8 + 2 * (lane & 3) + u > qrow)) v = -1e30f;
                    sacc[nt][hf * 2 + u] = v;
                    mx = fmaxf(mx, v);
                }
            mx = fmaxf(mx, __shfl_xor_sync(0xffffffffu, mx, 1));
            mx = fmaxf(mx, __shfl_xor_sync(0xffffffffu, mx, 2));
            float mnew = fmaxf(m[hf], mx);
            float corr = __expf(m[hf] - mnew);
            m[hf] = mnew;
            float ls = 0.f;
#pragma unroll
            for (int nt = 0; nt < 8; nt++)
#pragma unroll
                for (int u = 0; u < 2; u++) {
                    float p = __expf(sacc[nt][hf * 2 + u] - mnew);
                    sacc[nt][hf * 2 + u] = p;
                    ls += p;
                }
            ls += __shfl_xor_sync(0xffffffffu, ls, 1);
            ls += __shfl_xor_sync(0xffffffffu, ls, 2);
            l[hf] = l[hf] * corr + ls;
#pragma unroll
            for (int nt = 0; nt < 8; nt++)
#pragma unroll
                for (int u = 0; u < 2; u++) o[nt][hf * 2 + u] *= corr;
        }

        // ---- O += P V (P frags built in registers from sacc) ----
#pragma unroll
        for (int ks = 0; ks < 4; ks++) {
            uint32_t a0h = f2h2(sacc[2 * ks][0], sacc[2 * ks][1]);
            uint32_t a1h = f2h2(sacc[2 * ks][2], sacc[2 * ks][3]);
            uint32_t a2h = f2h2(sacc[2 * ks + 1][0], sacc[2 * ks + 1][1]);
            uint32_t a3h = f2h2(sacc[2 * ks + 1][2], sacc[2 * ks + 1][3]);
            uint32_t a0l = f2h2_lo(sacc[2 * ks][0], sacc[2 * ks][1], a0h);
            uint32_t a1l = f2h2_lo(sacc[2 * ks][2], sacc[2 * ks][3], a1h);
            uint32_t a2l = f2h2_lo(sacc[2 * ks + 1][0], sacc[2 * ks + 1][1], a2h);
            uint32_t a3l = f2h2_lo(sacc[2 * ks + 1][2], sacc[2 * ks + 1][3], a3h);
#pragma unroll
            for (int p = 0; p < 4; p++) {
                uint32_t offB = (uint32_t)((p * 16 + b_row) * AST + ks * 16 + b_col) * 2;
                uint32_t bh0, bh1, bh2, bh3, bl0, bl1, bl2, bl3;
                LDSM_X4(bh0, bh1, bh2, bh3, vhi_b + offB);
                LDSM_X4(bl0, bl1, bl2, bl3, vlo_b + offB);
                MMA16816(o[p * 2 + 0], a0h, a1h, a2h, a3h, bh0, bh1);
                MMA16816(o[p * 2 + 0], a0h, a1h, a2h, a3h, bl0, bl1);
                MMA16816(o[p * 2 + 0], a0l, a1l, a2l, a3l, bh0, bh1);
                MMA16816(o[p * 2 + 1], a0h, a1h, a2h, a3h, bh2, bh3);
                MMA16816(o[p * 2 + 1], a0h, a1h, a2h, a3h, bl2, bl3);
                MMA16816(o[p * 2 + 1], a0l, a1l, a2l, a3l, bh2, bh3);
            }
        }
    }

    // Epilogue: y -> hi/lo halves
    float inv0 = 1.f / l[0], inv1 = 1.f / l[1];
#pragma unroll
    for (int nt = 0; nt < 8; nt++) {
        const int row = qt * 128 + wid * 16 + (lane >> 2);
        const int col = h * HD_ + nt * 8 + 2 * (lane & 3);
#pragma unroll
        for (int rr = 0; rr < 2; rr++) {
            float inv = rr ? inv1 : inv0;
            float v0 = o[nt][rr * 2] * inv, v1 = o[nt][rr * 2 + 1] * inv;
            size_t idx = ((size_t)b * T_ + row + rr * 8) * D_ + col;
            uint32_t hi = f2h2(v0, v1);
            uint32_t lo = f2h2_lo(v0, v1, hi);
            *(uint32_t*)(g_yhi + idx) = hi;
            *(uint32_t*)(g_ylo + idx) = lo;
        }
    }
}

// ---------------------------------------------------------------------------
extern "C" void kernel_launch(void* const* d_in, const int* in_sizes, int n_in,
                              void* d_out, int out_size)
{
    const float* x      = (const float*)d_in[0];
    const float* w_qkv  = (const float*)d_in[1];
    const float* w_proj = (const float*)d_in[2];
    float* out = (float*)d_out;

    static bool attr_set = false;
    if (!attr_set) {
        cudaFuncSetAttribute(attn_hmma, cudaFuncAttributeMaxDynamicSharedMemorySize,
                             ATTN_SMEM);
        cudaFuncSetAttribute(hmma_gemm<3 * D_, D_, 1>,
                             cudaFuncAttributeMaxDynamicSharedMemorySize, GK_SMEM);
        cudaFuncSetAttribute(hmma_gemm<D_, D_, 0>,
                             cudaFuncAttributeMaxDynamicSharedMemorySize, GK_SMEM);
        attr_set = true;
    }

    __half *xhi, *xlo, *wqh, *wql, *wph, *wpl, *yhi, *ylo, *qkvh, *qkvl;
    cudaGetSymbolAddress((void**)&xhi, g_xhi);
    cudaGetSymbolAddress((void**)&xlo, g_xlo);
    cudaGetSymbolAddress((void**)&wqh, g_wqkvhi);
    cudaGetSymbolAddress((void**)&wql, g_wqkvlo);
    cudaGetSymbolAddress((void**)&wph, g_wphi);
    cudaGetSymbolAddress((void**)&wpl, g_wplo);
    cudaGetSymbolAddress((void**)&yhi, g_yhi);
    cudaGetSymbolAddress((void**)&ylo, g_ylo);
    cudaGetSymbolAddress((void**)&qkvh, g_qkvhi);
    cudaGetSymbolAddress((void**)&qkvl, g_qkvlo);

    // Split inputs
    {
        int n4 = M_ROWS * D_ / 4;
        split_kernel<<<(n4 + 255) / 256, 256>>>(x, xhi, xlo, n4);
        n4 = 3 * D_ * D_ / 4;
        split_kernel<<<(n4 + 255) / 256, 256>>>(w_qkv, wqh, wql, n4);
        n4 = D_ * D_ / 4;
        split_kernel<<<(n4 + 255) / 256, 256>>>(w_proj, wph, wpl, n4);
    }

    // QKV GEMM -> hi/lo halves
    {
        dim3 grid(3 * D_ / 128, M_ROWS / 128);
        hmma_gemm<3 * D_, D_, 1><<<grid, 256, GK_SMEM>>>(xhi, xlo, wqh, wql,
                                                         nullptr, qkvh, qkvl);
    }

    // HMMA attention -> y hi/lo
    {
        dim3 grid(T_ / 128, B_ * H_);
        attn_hmma<<<grid, 256, ATTN_SMEM>>>();
    }

    // Proj GEMM -> fp32 out
    {
        dim3 grid(D_ / 128, M_ROWS / 128);
        hmma_gemm<D_, D_, 0><<<grid, 256, GK_SMEM>>>(yhi, ylo, wph, wpl,
                                                     out, nullptr, nullptr);
    }
}

// round 8
// speedup vs baseline: 5.2894x; 1.3070x over previous
#include <cuda_runtime.h>
#include <cuda_fp16.h>
#include <cstdint>

// Problem constants
#define B_  2
#define T_  2048
#define D_  1024
#define H_  16
#define HD_ 64
#define M_ROWS (B_ * T_)   // 4096

// ---------------------------------------------------------------------------
// Scratch (allocation-free rule: __device__ globals)
// ---------------------------------------------------------------------------
__device__ __half g_xhi[(size_t)M_ROWS * D_];
__device__ __half g_xlo[(size_t)M_ROWS * D_];
__device__ __half g_wqkvhi[(size_t)3 * D_ * D_];
__device__ __half g_wqkvlo[(size_t)3 * D_ * D_];
__device__ __half g_wphi[(size_t)D_ * D_];
__device__ __half g_wplo[(size_t)D_ * D_];
__device__ __half g_qkvhi[(size_t)M_ROWS * 3 * D_];
__device__ __half g_qkvlo[(size_t)M_ROWS * 3 * D_];
__device__ __half g_yhi[(size_t)M_ROWS * D_];
__device__ __half g_ylo[(size_t)M_ROWS * D_];

// ---------------------------------------------------------------------------
// Helpers (baseline PTX only)
// ---------------------------------------------------------------------------
__device__ __forceinline__ uint32_t smem_u32(const void* p) {
    uint32_t a;
    asm("{ .reg .u64 t; cvta.to.shared.u64 t, %1; cvt.u32.u64 %0, t; }" : "=r"(a) : "l"(p));
    return a;
}

#define CP_ASYNC16(dst, src) \
    asm volatile("cp.async.cg.shared.global [%0], [%1], 16;" :: "r"(dst), "l"(src) : "memory")
#define CP_COMMIT() asm volatile("cp.async.commit_group;" ::: "memory")
#define CP_WAIT2()  asm volatile("cp.async.wait_group 2;" ::: "memory")
#define CP_WAIT1()  asm volatile("cp.async.wait_group 1;" ::: "memory")
#define CP_WAIT0()  asm volatile("cp.async.wait_group 0;" ::: "memory")

#define LDSM_X4(r0, r1, r2, r3, addr)                                          \
    asm volatile("ldmatrix.sync.aligned.m8n8.x4.shared.b16 {%0,%1,%2,%3}, [%4];" \
                 : "=r"(r0), "=r"(r1), "=r"(r2), "=r"(r3) : "r"(addr))

#define LDSM_X4_T(r0, r1, r2, r3, addr)                                        \
    asm volatile("ldmatrix.sync.aligned.m8n8.x4.trans.shared.b16 {%0,%1,%2,%3}, [%4];" \
                 : "=r"(r0), "=r"(r1), "=r"(r2), "=r"(r3) : "r"(addr))

#define MMA16816(c, a0, a1, a2, a3, b0, b1)                                    \
    asm volatile("mma.sync.aligned.m16n8k16.row.col.f32.f16.f16.f32 "          \
                 "{%0,%1,%2,%3}, {%4,%5,%6,%7}, {%8,%9}, {%0,%1,%2,%3};"       \
                 : "+f"((c)[0]), "+f"((c)[1]), "+f"((c)[2]), "+f"((c)[3])      \
                 : "r"(a0), "r"(a1), "r"(a2), "r"(a3), "r"(b0), "r"(b1))

__device__ __forceinline__ uint32_t f2h2(float a, float b) {
    __half2 t = __floats2half2_rn(a, b);
    return *reinterpret_cast<uint32_t*>(&t);
}
__device__ __forceinline__ uint32_t f2h2_lo(float a, float b, uint32_t hi) {
    __half2 h = *reinterpret_cast<__half2*>(&hi);
    __half2 t = __floats2half2_rn(a - __low2float(h), b - __high2float(h));
    return *reinterpret_cast<uint32_t*>(&t);
}
// 64B-row swizzle: 8 consecutive rows hit 8 distinct 16B banks per chunk.
__device__ __forceinline__ uint32_t swz64(uint32_t off) {
    return off ^ (((off >> 7) & 3) << 4);
}

// ---------------------------------------------------------------------------
// Split kernel: fp32 -> (hi, lo) fp16
// ---------------------------------------------------------------------------
__global__ void split_kernel(const float* __restrict__ in, __half* __restrict__ hi,
                             __half* __restrict__ lo, int n4) {
    int i = blockIdx.x * blockDim.x + threadIdx.x;
    if (i >= n4) return;
    float4 v = ((const float4*)in)[i];
    float f[4] = {v.x, v.y, v.z, v.w};
    __half h[4], l[4];
#pragma unroll
    for (int j = 0; j < 4; j++) {
        h[j] = __float2half_rn(f[j]);
        l[j] = __float2half_rn(f[j] - __half2float(h[j]));
    }
    ((__half2*)hi)[i * 2 + 0] = __halves2half2(h[0], h[1]);
    ((__half2*)hi)[i * 2 + 1] = __halves2half2(h[2], h[3]);
    ((__half2*)lo)[i * 2 + 0] = __halves2half2(l[0], l[1]);
    ((__half2*)lo)[i * 2 + 1] = __halves2half2(l[2], l[3]);
}

// ---------------------------------------------------------------------------
// HMMA fp16-split GEMM (3 passes), 3-stage cp.async pipeline, 1 sync/iter.
// CTA 128x128, 8 warps (4M x 2N). BK=32. 64B smem rows + XOR swizzle.
// ---------------------------------------------------------------------------
#define GK_ARB  8192               // bytes per array (128 rows x 64 B)
#define GK_STGB 32768              // bytes per stage (Ahi,Alo,Bhi,Blo)
#define GK_SMEM (3 * GK_STGB)      // 98304 B

template <int N_, int K_, int OUT_SPLIT>
__global__ __launch_bounds__(256, 2) void hmma_gemm(
    const __half* __restrict__ Ahi, const __half* __restrict__ Alo,
    const __half* __restrict__ Bhi, const __half* __restrict__ Blo,
    float* __restrict__ C, __half* __restrict__ Chi, __half* __restrict__ Clo)
{
    extern __shared__ char sh[];
    const int tid = threadIdx.x;
    const int lane = tid & 31;
    const int wid = tid >> 5;
    const int wm = wid >> 1;
    const int wn = wid & 1;
    const int m0 = blockIdx.y * 128;
    const int n0 = blockIdx.x * 128;

    float acc[2][8][4];
#pragma unroll
    for (int mt = 0; mt < 2; mt++)
#pragma unroll
        for (int nt = 0; nt < 8; nt++)
#pragma unroll
            for (int q = 0; q < 4; q++) acc[mt][nt][q] = 0.f;

    const __half* gsrc[4] = {Ahi, Alo, Bhi, Blo};

    auto stage_load = [&](int s, int kt) {
        char* base = sh + s * GK_STGB;
#pragma unroll
        for (int arr = 0; arr < 4; arr++) {
            const __half* g = gsrc[arr];
            const int row0 = (arr < 2) ? m0 : n0;
#pragma unroll
            for (int i = 0; i < 2; i++) {
                int c = tid + i * 256;
                int row = c >> 2, seg = c & 3;
                uint32_t off = swz64((uint32_t)(row * 64 + seg * 16));
                uint32_t dst = smem_u32(base + arr * GK_ARB + off);
                const __half* src = g + (size_t)(row0 + row) * K_ + kt * 32 + seg * 8;
                CP_ASYNC16(dst, src);
            }
        }
    };

    const int a_row = (lane & 15);
    const int a_col = (lane >> 4) * 8;
    const int b_row = ((lane & 16) ? 8 : 0) + (lane & 7);
    const int b_col = ((lane & 8) ? 8 : 0);

    stage_load(0, 0); CP_COMMIT();
    stage_load(1, 1); CP_COMMIT();

    constexpr int KT = K_ / 32;
    for (int kt = 0; kt < KT; kt++) {
        if (kt + 1 < KT) CP_WAIT1(); else CP_WAIT0();
        __syncthreads();
        if (kt + 2 < KT) { stage_load((kt + 2) % 3, kt + 2); CP_COMMIT(); }

        const uint32_t ah_b = smem_u32(sh + (kt % 3) * GK_STGB);
        const uint32_t al_b = ah_b + GK_ARB;
        const uint32_t bh_b = ah_b + 2 * GK_ARB;
        const uint32_t bl_b = ah_b + 3 * GK_ARB;

#pragma unroll
        for (int ks = 0; ks < 2; ks++) {
            const int k0 = ks * 16;
            uint32_t bh[4][4], bl[4][4];
#pragma unroll
            for (int p = 0; p < 4; p++) {
                const int nB = wn * 64 + p * 16;
                uint32_t off = swz64((uint32_t)((nB + b_row) * 64 + (k0 + b_col) * 2));
                LDSM_X4(bh[p][0], bh[p][1], bh[p][2], bh[p][3], bh_b + off);
                LDSM_X4(bl[p][0], bl[p][1], bl[p][2], bl[p][3], bl_b + off);
            }
#pragma unroll
            for (int mt = 0; mt < 2; mt++) {
                const int rA = wm * 32 + mt * 16;
                uint32_t off = swz64((uint32_t)((rA + a_row) * 64 + (k0 + a_col) * 2));
                uint32_t ah0, ah1, ah2, ah3, al0, al1, al2, al3;
                LDSM_X4(ah0, ah1, ah2, ah3, ah_b + off);
                LDSM_X4(al0, al1, al2, al3, al_b + off);
#pragma unroll
                for (int p = 0; p < 4; p++) {
#pragma unroll
                    for (int t = 0; t < 2; t++) {
                        const int nt = p * 2 + t;
                        MMA16816(acc[mt][nt], ah0, ah1, ah2, ah3, bh[p][t * 2], bh[p][t * 2 + 1]);
                        MMA16816(acc[mt][nt], ah0, ah1, ah2, ah3, bl[p][t * 2], bl[p][t * 2 + 1]);
                        MMA16816(acc[mt][nt], al0, al1, al2, al3, bh[p][t * 2], bh[p][t * 2 + 1]);
                    }
                }
            }
        }
    }

#pragma unroll
    for (int mt = 0; mt < 2; mt++) {
#pragma unroll
        for (int nt = 0; nt < 8; nt++) {
            const int row = m0 + wm * 32 + mt * 16 + (lane >> 2);
            const int col = n0 + wn * 64 + nt * 8 + 2 * (lane & 3);
#pragma unroll
            for (int rr = 0; rr < 2; rr++) {
                float c0 = acc[mt][nt][rr * 2], c1 = acc[mt][nt][rr * 2 + 1];
                size_t idx = (size_t)(row + rr * 8) * N_ + col;
                if (OUT_SPLIT) {
                    uint32_t hi = f2h2(c0, c1);
                    uint32_t lo = f2h2_lo(c0, c1, hi);
                    *(uint32_t*)(Chi + idx) = hi;
                    *(uint32_t*)(Clo + idx) = lo;
                } else {
                    *(float2*)(C + idx) = make_float2(c0, c1);
                }
            }
        }
    }
}

// ---------------------------------------------------------------------------
// HMMA flash attention (causal). CTA: 128 q-rows x one (b,h); BKV=64.
// 4-stage cp.async K/V pipeline, 1 sync per tile. V via ldmatrix.trans
// (no smem transpose). 8 warps x (16 rows x 64 cols). smem stride 72 halves.
// ---------------------------------------------------------------------------
#define AST 72
#define KV_ARB  (64 * AST * 2)            // 9216 B per K/V array
#define KV_STGB (4 * KV_ARB)              // 36864 B per stage
#define Q_ARB   (128 * AST * 2)           // 18432 B
#define ATTN_SMEM (2 * Q_ARB + 4 * KV_STGB)  // 184320 B

__global__ __launch_bounds__(256, 1) void attn_hmma()
{
    extern __shared__ char sha[];
    __half* Qhi = (__half*)sha;
    __half* Qlo = (__half*)(sha + Q_ARB);
    char* kv0 = sha + 2 * Q_ARB;

    const int tid = threadIdx.x;
    const int lane = tid & 31;
    const int wid = tid >> 5;
    const int qt = (int)gridDim.x - 1 - (int)blockIdx.x;   // heavy CTAs first
    const int bh = blockIdx.y;
    const int b = bh >> 4;
    const int h = bh & 15;

    const __half* ghi = g_qkvhi + (size_t)b * T_ * (3 * D_) + h * HD_;
    const __half* glo = g_qkvlo + (size_t)b * T_ * (3 * D_) + h * HD_;

    auto kv_load = [&](int s, int j) {
        char* base = kv0 + s * KV_STGB;
#pragma unroll
        for (int i = 0; i < 2; i++) {
            int c = tid + i * 256;
            int row = c >> 3, seg = c & 7;
            size_t gb = (size_t)(j * 64 + row) * (3 * D_) + seg * 8;
            uint32_t doff = (uint32_t)(row * AST + seg * 8) * 2;
            CP_ASYNC16(smem_u32(base + 0 * KV_ARB + doff), ghi + gb + D_);
            CP_ASYNC16(smem_u32(base + 1 * KV_ARB + doff), glo + gb + D_);
            CP_ASYNC16(smem_u32(base + 2 * KV_ARB + doff), ghi + gb + 2 * D_);
            CP_ASYNC16(smem_u32(base + 3 * KV_ARB + doff), glo + gb + 2 * D_);
        }
    };

    // Load Q (plain; covered by first barrier)
#pragma unroll
    for (int i = 0; i < 4; i++) {
        int c = tid + i * 256;
        int r = c >> 3, d8 = (c & 7) * 8;
        size_t g = (size_t)(qt * 128 + r) * (3 * D_) + d8;
        *(uint4*)&Qhi[r * AST + d8] = *(const uint4*)(ghi + g);
        *(uint4*)&Qlo[r * AST + d8] = *(const uint4*)(glo + g);
    }

    kv_load(0, 0); CP_COMMIT();
    kv_load(1, 1); CP_COMMIT();

    float o[8][4];
    float m[2] = {-1e30f, -1e30f}, l[2] = {0.f, 0.f};
#pragma unroll
    for (int nt = 0; nt < 8; nt++)
#pragma unroll
        for (int q = 0; q < 4; q++) o[nt][q] = 0.f;

    const int a_row = (lane & 15);
    const int a_col = (lane >> 4) * 8;
    const int b_row = ((lane & 16) ? 8 : 0) + (lane & 7);
    const int b_col = ((lane & 8) ? 8 : 0);
    const int t_row = (lane & 15);            // trans-ldmatrix: kv offset
    const int t_col = ((lane >> 4) & 1) * 8;  // trans-ldmatrix: d offset

    const uint32_t qhi_b = smem_u32(Qhi), qlo_b = smem_u32(Qlo);

    const int JT = 2 * qt + 2;
    for (int j0 = 0; j0 < JT; j0++) {
        if (j0 + 2 < JT) { kv_load((j0 + 2) & 3, j0 + 2); CP_COMMIT(); CP_WAIT2(); }
        else if (j0 + 1 < JT) CP_WAIT1();
        else CP_WAIT0();
        __syncthreads();

        const uint32_t khi_b = smem_u32(kv0 + (j0 & 3) * KV_STGB);
        const uint32_t klo_b = khi_b + KV_ARB;
        const uint32_t vhi_b = khi_b + 2 * KV_ARB;
        const uint32_t vlo_b = khi_b + 3 * KV_ARB;

        // ---- S = Q K^T (3-pass) ----
        float sacc[8][4];
#pragma unroll
        for (int nt = 0; nt < 8; nt++)
#pragma unroll
            for (int q = 0; q < 4; q++) sacc[nt][q] = 0.f;

#pragma unroll
        for (int ks = 0; ks < 4; ks++) {
            uint32_t offA = (uint32_t)((wid * 16 + a_row) * AST + ks * 16 + a_col) * 2;
            uint32_t ah0, ah1, ah2, ah3, al0, al1, al2, al3;
            LDSM_X4(ah0, ah1, ah2, ah3, qhi_b + offA);
            LDSM_X4(al0, al1, al2, al3, qlo_b + offA);
            uint32_t bhf[4][4], blf[4][4];
#pragma unroll
            for (int p = 0; p < 4; p++) {
                uint32_t offB = (uint32_t)((p * 16 + b_row) * AST + ks * 16 + b_col) * 2;
                LDSM_X4(bhf[p][0], bhf[p][1], bhf[p][2], bhf[p][3], khi_b + offB);
                LDSM_X4(blf[p][0], blf[p][1], blf[p][2], blf[p][3], klo_b + offB);
            }
#pragma unroll
            for (int p = 0; p < 4; p++)
#pragma unroll
                for (int t = 0; t < 2; t++) {
                    const int nt = p * 2 + t;
                    MMA16816(sacc[nt], ah0, ah1, ah2, ah3, bhf[p][t * 2], bhf[p][t * 2 + 1]);
                    MMA16816(sacc[nt], ah0, ah1, ah2, ah3, blf[p][t * 2], blf[p][t * 2 + 1]);
                    MMA16816(sacc[nt], al0, al1, al2, al3, bhf[p][t * 2], bhf[p][t * 2 + 1]);
                }
        }

        // ---- softmax ----
        const bool need_mask = (j0 >= 2 * qt);
#pragma unroll
        for (int hf = 0; hf < 2; hf++) {
            const int qrow = qt * 128 + wid * 16 + (lane >> 2) + hf * 8;
            float mx = -1e30f;
#pragma unroll
            for (int nt = 0; nt < 8; nt++)
#pragma unroll
                for (int u = 0; u < 2; u++) {
                    float v = sacc[nt][hf * 2 + u] * 0.125f;
                    if (need_mask && (j0 * 64 + nt * 8 + 2 * (lane & 3) + u > qrow)) v = -1e30f;
                    sacc[nt][hf * 2 + u] = v;
                    mx = fmaxf(mx, v);
                }
            mx = fmaxf(mx, __shfl_xor_sync(0xffffffffu, mx, 1));
            mx = fmaxf(mx, __shfl_xor_sync(0xffffffffu, mx, 2));
            float mnew = fmaxf(m[hf], mx);
            float corr = __expf(m[hf] - mnew);
            m[hf] = mnew;
            float ls = 0.f;
#pragma unroll
            for (int nt = 0; nt < 8; nt++)
#pragma unroll
                for (int u = 0; u < 2; u++) {
                    float p = __expf(sacc[nt][hf * 2 + u] - mnew);
                    sacc[nt][hf * 2 + u] = p;
                    ls += p;
                }
            ls += __shfl_xor_sync(0xffffffffu, ls, 1);
            ls += __shfl_xor_sync(0xffffffffu, ls, 2);
            l[hf] = l[hf] * corr + ls;
#pragma unroll
            for (int nt = 0; nt < 8; nt++)
#pragma unroll
                for (int u = 0; u < 2; u++) o[nt][hf * 2 + u] *= corr;
        }

        // ---- O += P V (P frags in registers; V via ldmatrix.trans) ----
#pragma unroll
        for (int ks = 0; ks < 4; ks++) {
            uint32_t a0h = f2h2(sacc[2 * ks][0], sacc[2 * ks][1]);
            uint32_t a1h = f2h2(sacc[2 * ks][2], sacc[2 * ks][3]);
            uint32_t a2h = f2h2(sacc[2 * ks + 1][0], sacc[2 * ks + 1][1]);
            uint32_t a3h = f2h2(sacc[2 * ks + 1][2], sacc[2 * ks + 1][3]);
            uint32_t a0l = f2h2_lo(sacc[2 * ks][0], sacc[2 * ks][1], a0h);
            uint32_t a1l = f2h2_lo(sacc[2 * ks][2], sacc[2 * ks][3], a1h);
            uint32_t a2l = f2h2_lo(sacc[2 * ks + 1][0], sacc[2 * ks + 1][1], a2h);
            uint32_t a3l = f2h2_lo(sacc[2 * ks + 1][2], sacc[2 * ks + 1][3], a3h);
#pragma unroll
            for (int p = 0; p < 4; p++) {
                uint32_t offV = (uint32_t)((ks * 16 + t_row) * AST + p * 16 + t_col) * 2;
                uint32_t bh0, bh1, bh2, bh3, bl0, bl1, bl2, bl3;
                LDSM_X4_T(bh0, bh1, bh2, bh3, vhi_b + offV);
                LDSM_X4_T(bl0, bl1, bl2, bl3, vlo_b + offV);
                MMA16816(o[p * 2 + 0], a0h, a1h, a2h, a3h, bh0, bh1);
                MMA16816(o[p * 2 + 0], a0h, a1h, a2h, a3h, bl0, bl1);
                MMA16816(o[p * 2 + 0], a0l, a1l, a2l, a3l, bh0, bh1);
                MMA16816(o[p * 2 + 1], a0h, a1h, a2h, a3h, bh2, bh3);
                MMA16816(o[p * 2 + 1], a0h, a1h, a2h, a3h, bl2, bl3);
                MMA16816(o[p * 2 + 1], a0l, a1l, a2l, a3l, bh2, bh3);
            }
        }
    }

    // Epilogue: y -> hi/lo halves
    float inv0 = 1.f / l[0], inv1 = 1.f / l[1];
#pragma unroll
    for (int nt = 0; nt < 8; nt++) {
        const int row = qt * 128 + wid * 16 + (lane >> 2);
        const int col = h * HD_ + nt * 8 + 2 * (lane & 3);
#pragma unroll
        for (int rr = 0; rr < 2; rr++) {
            float inv = rr ? inv1 : inv0;
            float v0 = o[nt][rr * 2] * inv, v1 = o[nt][rr * 2 + 1] * inv;
            size_t idx = ((size_t)b * T_ + row + rr * 8) * D_ + col;
            uint32_t hi = f2h2(v0, v1);
            uint32_t lo = f2h2_lo(v0, v1, hi);
            *(uint32_t*)(g_yhi + idx) = hi;
            *(uint32_t*)(g_ylo + idx) = lo;
        }
    }
}

// ---------------------------------------------------------------------------
extern "C" void kernel_launch(void* const* d_in, const int* in_sizes, int n_in,
                              void* d_out, int out_size)
{
    const float* x      = (const float*)d_in[0];
    const float* w_qkv  = (const float*)d_in[1];
    const float* w_proj = (const float*)d_in[2];
    float* out = (float*)d_out;

    static bool attr_set = false;
    if (!attr_set) {
        cudaFuncSetAttribute(attn_hmma, cudaFuncAttributeMaxDynamicSharedMemorySize,
                             ATTN_SMEM);
        cudaFuncSetAttribute(hmma_gemm<3 * D_, D_, 1>,
                             cudaFuncAttributeMaxDynamicSharedMemorySize, GK_SMEM);
        cudaFuncSetAttribute(hmma_gemm<D_, D_, 0>,
                             cudaFuncAttributeMaxDynamicSharedMemorySize, GK_SMEM);
        attr_set = true;
    }

    __half *xhi, *xlo, *wqh, *wql, *wph, *wpl, *yhi, *ylo, *qkvh, *qkvl;
    cudaGetSymbolAddress((void**)&xhi, g_xhi);
    cudaGetSymbolAddress((void**)&xlo, g_xlo);
    cudaGetSymbolAddress((void**)&wqh, g_wqkvhi);
    cudaGetSymbolAddress((void**)&wql, g_wqkvlo);
    cudaGetSymbolAddress((void**)&wph, g_wphi);
    cudaGetSymbolAddress((void**)&wpl, g_wplo);
    cudaGetSymbolAddress((void**)&yhi, g_yhi);
    cudaGetSymbolAddress((void**)&ylo, g_ylo);
    cudaGetSymbolAddress((void**)&qkvh, g_qkvhi);
    cudaGetSymbolAddress((void**)&qkvl, g_qkvlo);

    // Split inputs
    {
        int n4 = M_ROWS * D_ / 4;
        split_kernel<<<(n4 + 255) / 256, 256>>>(x, xhi, xlo, n4);
        n4 = 3 * D_ * D_ / 4;
        split_kernel<<<(n4 + 255) / 256, 256>>>(w_qkv, wqh, wql, n4);
        n4 = D_ * D_ / 4;
        split_kernel<<<(n4 + 255) / 256, 256>>>(w_proj, wph, wpl, n4);
    }

    // QKV GEMM -> hi/lo halves
    {
        dim3 grid(3 * D_ / 128, M_ROWS / 128);
        hmma_gemm<3 * D_, D_, 1><<<grid, 256, GK_SMEM>>>(xhi, xlo, wqh, wql,
                                                         nullptr, qkvh, qkvl);
    }

    // HMMA attention -> y hi/lo
    {
        dim3 grid(T_ / 128, B_ * H_);
        attn_hmma<<<grid, 256, ATTN_SMEM>>>();
    }

    // Proj GEMM -> fp32 out
    {
        dim3 grid(D_ / 128, M_ROWS / 128);
        hmma_gemm<D_, D_, 0><<<grid, 256, GK_SMEM>>>(yhi, ylo, wph, wpl,
                                                     out, nullptr, nullptr);
    }
}

// round 10
// speedup vs baseline: 5.6063x; 1.0599x over previous
#include <cuda_runtime.h>
#include <cuda_fp16.h>
#include <cstdint>

// Problem constants
#define B_  2
#define T_  2048
#define D_  1024
#define H_  16
#define HD_ 64
#define M_ROWS (B_ * T_)   // 4096

// ---------------------------------------------------------------------------
// Scratch (allocation-free rule: __device__ globals)
// ---------------------------------------------------------------------------
__device__ __half g_xhi[(size_t)M_ROWS * D_];
__device__ __half g_xlo[(size_t)M_ROWS * D_];
__device__ __half g_wqkvhi[(size_t)3 * D_ * D_];
__device__ __half g_wqkvlo[(size_t)3 * D_ * D_];
__device__ __half g_wphi[(size_t)D_ * D_];
__device__ __half g_wplo[(size_t)D_ * D_];
__device__ __half g_qkvhi[(size_t)M_ROWS * 3 * D_];
__device__ __half g_qkvlo[(size_t)M_ROWS * 3 * D_];
__device__ __half g_yhi[(size_t)M_ROWS * D_];
__device__ __half g_ylo[(size_t)M_ROWS * D_];

// ---------------------------------------------------------------------------
// Helpers (baseline PTX only)
// ---------------------------------------------------------------------------
__device__ __forceinline__ uint32_t smem_u32(const void* p) {
    uint32_t a;
    asm("{ .reg .u64 t; cvta.to.shared.u64 t, %1; cvt.u32.u64 %0, t; }" : "=r"(a) : "l"(p));
    return a;
}

#define CP_ASYNC16(dst, src) \
    asm volatile("cp.async.cg.shared.global [%0], [%1], 16;" :: "r"(dst), "l"(src) : "memory")
#define CP_COMMIT() asm volatile("cp.async.commit_group;" ::: "memory")
#define CP_WAIT2()  asm volatile("cp.async.wait_group 2;" ::: "memory")
#define CP_WAIT1()  asm volatile("cp.async.wait_group 1;" ::: "memory")
#define CP_WAIT0()  asm volatile("cp.async.wait_group 0;" ::: "memory")

#define LDSM_X4(r0, r1, r2, r3, addr)                                          \
    asm volatile("ldmatrix.sync.aligned.m8n8.x4.shared.b16 {%0,%1,%2,%3}, [%4];" \
                 : "=r"(r0), "=r"(r1), "=r"(r2), "=r"(r3) : "r"(addr))

#define LDSM_X4_T(r0, r1, r2, r3, addr)                                        \
    asm volatile("ldmatrix.sync.aligned.m8n8.x4.trans.shared.b16 {%0,%1,%2,%3}, [%4];" \
                 : "=r"(r0), "=r"(r1), "=r"(r2), "=r"(r3) : "r"(addr))

#define MMA16816(c, a0, a1, a2, a3, b0, b1)                                    \
    asm volatile("mma.sync.aligned.m16n8k16.row.col.f32.f16.f16.f32 "          \
                 "{%0,%1,%2,%3}, {%4,%5,%6,%7}, {%8,%9}, {%0,%1,%2,%3};"       \
                 : "+f"((c)[0]), "+f"((c)[1]), "+f"((c)[2]), "+f"((c)[3])      \
                 : "r"(a0), "r"(a1), "r"(a2), "r"(a3), "r"(b0), "r"(b1))

__device__ __forceinline__ uint32_t f2h2(float a, float b) {
    __half2 t = __floats2half2_rn(a, b);
    return *reinterpret_cast<uint32_t*>(&t);
}
__device__ __forceinline__ uint32_t f2h2_lo(float a, float b, uint32_t hi) {
    __half2 h = *reinterpret_cast<__half2*>(&hi);
    __half2 t = __floats2half2_rn(a - __low2float(h), b - __high2float(h));
    return *reinterpret_cast<uint32_t*>(&t);
}
// 64B-row swizzle: 8 consecutive rows hit 8 distinct 16B banks per chunk.
__device__ __forceinline__ uint32_t swz64(uint32_t off) {
    return off ^ (((off >> 7) & 3) << 4);
}

// ---------------------------------------------------------------------------
// Split kernel: fp32 -> (hi, lo) fp16
// ---------------------------------------------------------------------------
__global__ void split_kernel(const float* __restrict__ in, __half* __restrict__ hi,
                             __half* __restrict__ lo, int n4) {
    int i = blockIdx.x * blockDim.x + threadIdx.x;
    if (i >= n4) return;
    float4 v = ((const float4*)in)[i];
    float f[4] = {v.x, v.y, v.z, v.w};
    __half h[4], l[4];
#pragma unroll
    for (int j = 0; j < 4; j++) {
        h[j] = __float2half_rn(f[j]);
        l[j] = __float2half_rn(f[j] - __half2float(h[j]));
    }
    ((__half2*)hi)[i * 2 + 0] = __halves2half2(h[0], h[1]);
    ((__half2*)hi)[i * 2 + 1] = __halves2half2(h[2], h[3]);
    ((__half2*)lo)[i * 2 + 0] = __halves2half2(l[0], l[1]);
    ((__half2*)lo)[i * 2 + 1] = __halves2half2(l[2], l[3]);
}

// ---------------------------------------------------------------------------
// HMMA fp16-split GEMM (3 passes), 3-stage cp.async pipeline, 1 sync/iter.
// CTA 128x128, 4 warps (2M x 2N), warp 64x64 -> 16 LDSM : 96 MMA per k16
// (MMA-bound). 2 CTAs/SM. 64B smem rows + XOR swizzle.
// ---------------------------------------------------------------------------
#define GK_ARB  8192               // bytes per array (128 rows x 64 B)
#define GK_STGB 32768              // bytes per stage (Ahi,Alo,Bhi,Blo)
#define GK_SMEM (3 * GK_STGB)      // 98304 B

template <int N_, int K_, int OUT_SPLIT>
__global__ __launch_bounds__(128, 2) void hmma_gemm(
    const __half* __restrict__ Ahi, const __half* __restrict__ Alo,
    const __half* __restrict__ Bhi, const __half* __restrict__ Blo,
    float* __restrict__ C, __half* __restrict__ Chi, __half* __restrict__ Clo)
{
    extern __shared__ char sh[];
    const int tid = threadIdx.x;
    const int lane = tid & 31;
    const int wid = tid >> 5;
    const int wm = wid >> 1;          // 0..1 -> 64-row slab
    const int wn = wid & 1;           // 0..1 -> 64-col slab
    const int m0 = blockIdx.y * 128;
    const int n0 = blockIdx.x * 128;

    float acc[4][8][4];
#pragma unroll
    for (int mt = 0; mt < 4; mt++)
#pragma unroll
        for (int nt = 0; nt < 8; nt++)
#pragma unroll
            for (int q = 0; q < 4; q++) acc[mt][nt][q] = 0.f;

    const __half* gsrc[4] = {Ahi, Alo, Bhi, Blo};

    auto stage_load = [&](int s, int kt) {
        char* base = sh + s * GK_STGB;
#pragma unroll
        for (int arr = 0; arr < 4; arr++) {
            const __half* g = gsrc[arr];
            const int row0 = (arr < 2) ? m0 : n0;
#pragma unroll
            for (int i = 0; i < 4; i++) {
                int c = tid + i * 128;
                int row = c >> 2, seg = c & 3;
                uint32_t off = swz64((uint32_t)(row * 64 + seg * 16));
                uint32_t dst = smem_u32(base + arr * GK_ARB + off);
                const __half* src = g + (size_t)(row0 + row) * K_ + kt * 32 + seg * 8;
                CP_ASYNC16(dst, src);
            }
        }
    };

    const int a_row = (lane & 15);
    const int a_col = (lane >> 4) * 8;
    const int b_row = ((lane & 16) ? 8 : 0) + (lane & 7);
    const int b_col = ((lane & 8) ? 8 : 0);

    stage_load(0, 0); CP_COMMIT();
    stage_load(1, 1); CP_COMMIT();

    constexpr int KT = K_ / 32;
    for (int kt = 0; kt < KT; kt++) {
        if (kt + 1 < KT) CP_WAIT1(); else CP_WAIT0();
        __syncthreads();
        if (kt + 2 < KT) { stage_load((kt + 2) % 3, kt + 2); CP_COMMIT(); }

        const uint32_t ah_b = smem_u32(sh + (kt % 3) * GK_STGB);
        const uint32_t al_b = ah_b + GK_ARB;
        const uint32_t bh_b = ah_b + 2 * GK_ARB;
        const uint32_t bl_b = ah_b + 3 * GK_ARB;

#pragma unroll
        for (int ks = 0; ks < 2; ks++) {
            const int k0 = ks * 16;
            uint32_t bh[4][4], bl[4][4];
#pragma unroll
            for (int p = 0; p < 4; p++) {
                const int nB = wn * 64 + p * 16;
                uint32_t off = swz64((uint32_t)((nB + b_row) * 64 + (k0 + b_col) * 2));
                LDSM_X4(bh[p][0], bh[p][1], bh[p][2], bh[p][3], bh_b + off);
                LDSM_X4(bl[p][0], bl[p][1], bl[p][2], bl[p][3], bl_b + off);
            }
#pragma unroll
            for (int mt = 0; mt < 4; mt++) {
                const int rA = wm * 64 + mt * 16;
                uint32_t off = swz64((uint32_t)((rA + a_row) * 64 + (k0 + a_col) * 2));
                uint32_t ah0, ah1, ah2, ah3, al0, al1, al2, al3;
                LDSM_X4(ah0, ah1, ah2, ah3, ah_b + off);
                LDSM_X4(al0, al1, al2, al3, al_b + off);
#pragma unroll
                for (int p = 0; p < 4; p++) {
#pragma unroll
                    for (int t = 0; t < 2; t++) {
                        const int nt = p * 2 + t;
                        MMA16816(acc[mt][nt], ah0, ah1, ah2, ah3, bh[p][t * 2], bh[p][t * 2 + 1]);
                        MMA16816(acc[mt][nt], ah0, ah1, ah2, ah3, bl[p][t * 2], bl[p][t * 2 + 1]);
                        MMA16816(acc[mt][nt], al0, al1, al2, al3, bh[p][t * 2], bh[p][t * 2 + 1]);
                    }
                }
            }
        }
    }

#pragma unroll
    for (int mt = 0; mt < 4; mt++) {
#pragma unroll
        for (int nt = 0; nt < 8; nt++) {
            const int row = m0 + wm * 64 + mt * 16 + (lane >> 2);
            const int col = n0 + wn * 64 + nt * 8 + 2 * (lane & 3);
#pragma unroll
            for (int rr = 0; rr < 2; rr++) {
                float c0 = acc[mt][nt][rr * 2], c1 = acc[mt][nt][rr * 2 + 1];
                size_t idx = (size_t)(row + rr * 8) * N_ + col;
                if (OUT_SPLIT) {
                    uint32_t hi = f2h2(c0, c1);
                    uint32_t lo = f2h2_lo(c0, c1, hi);
                    *(uint32_t*)(Chi + idx) = hi;
                    *(uint32_t*)(Clo + idx) = lo;
                } else {
                    *(float2*)(C + idx) = make_float2(c0, c1);
                }
            }
        }
    }
}

// ---------------------------------------------------------------------------
// HMMA flash attention (causal). CTA: 128 q-rows x one (b,h); BKV=64.
// 4-stage cp.async K/V pipeline, 1 sync per tile. V via ldmatrix.trans.
// 8 warps x (16 rows x 64 cols). smem stride 72 halves. (Unchanged — measured
// ~184us in R8.)
// ---------------------------------------------------------------------------
#define AST 72
#define KV_ARB  (64 * AST * 2)            // 9216 B per K/V array
#define KV_STGB (4 * KV_ARB)              // 36864 B per stage
#define Q_ARB   (128 * AST * 2)           // 18432 B
#define ATTN_SMEM (2 * Q_ARB + 4 * KV_STGB)  // 184320 B

__global__ __launch_bounds__(256, 1) void attn_hmma()
{
    extern __shared__ char sha[];
    __half* Qhi = (__half*)sha;
    __half* Qlo = (__half*)(sha + Q_ARB);
    char* kv0 = sha + 2 * Q_ARB;

    const int tid = threadIdx.x;
    const int lane = tid & 31;
    const int wid = tid >> 5;
    const int qt = (int)gridDim.x - 1 - (int)blockIdx.x;   // heavy CTAs first
    const int bh = blockIdx.y;
    const int b = bh >> 4;
    const int h = bh & 15;

    const __half* ghi = g_qkvhi + (size_t)b * T_ * (3 * D_) + h * HD_;
    const __half* glo = g_qkvlo + (size_t)b * T_ * (3 * D_) + h * HD_;

    auto kv_load = [&](int s, int j) {
        char* base = kv0 + s * KV_STGB;
#pragma unroll
        for (int i = 0; i < 2; i++) {
            int c = tid + i * 256;
            int row = c >> 3, seg = c & 7;
            size_t gb = (size_t)(j * 64 + row) * (3 * D_) + seg * 8;
            uint32_t doff = (uint32_t)(row * AST + seg * 8) * 2;
            CP_ASYNC16(smem_u32(base + 0 * KV_ARB + doff), ghi + gb + D_);
            CP_ASYNC16(smem_u32(base + 1 * KV_ARB + doff), glo + gb + D_);
            CP_ASYNC16(smem_u32(base + 2 * KV_ARB + doff), ghi + gb + 2 * D_);
            CP_ASYNC16(smem_u32(base + 3 * KV_ARB + doff), glo + gb + 2 * D_);
        }
    };

    // Load Q (plain; covered by first barrier)
#pragma unroll
    for (int i = 0; i < 4; i++) {
        int c = tid + i * 256;
        int r = c >> 3, d8 = (c & 7) * 8;
        size_t g = (size_t)(qt * 128 + r) * (3 * D_) + d8;
        *(uint4*)&Qhi[r * AST + d8] = *(const uint4*)(ghi + g);
        *(uint4*)&Qlo[r * AST + d8] = *(const uint4*)(glo + g);
    }

    kv_load(0, 0); CP_COMMIT();
    kv_load(1, 1); CP_COMMIT();

    float o[8][4];
    float m[2] = {-1e30f, -1e30f}, l[2] = {0.f, 0.f};
#pragma unroll
    for (int nt = 0; nt < 8; nt++)
#pragma unroll
        for (int q = 0; q < 4; q++) o[nt][q] = 0.f;

    const int a_row = (lane & 15);
    const int a_col = (lane >> 4) * 8;
    const int b_row = ((lane & 16) ? 8 : 0) + (lane & 7);
    const int b_col = ((lane & 8) ? 8 : 0);
    const int t_row = (lane & 15);
    const int t_col = ((lane >> 4) & 1) * 8;

    const uint32_t qhi_b = smem_u32(Qhi), qlo_b = smem_u32(Qlo);

    const int JT = 2 * qt + 2;
    for (int j0 = 0; j0 < JT; j0++) {
        if (j0 + 2 < JT) { kv_load((j0 + 2) & 3, j0 + 2); CP_COMMIT(); CP_WAIT2(); }
        else if (j0 + 1 < JT) CP_WAIT1();
        else CP_WAIT0();
        __syncthreads();

        const uint32_t khi_b = smem_u32(kv0 + (j0 & 3) * KV_STGB);
        const uint32_t klo_b = khi_b + KV_ARB;
        const uint32_t vhi_b = khi_b + 2 * KV_ARB;
        const uint32_t vlo_b = khi_b + 3 * KV_ARB;

        // ---- S = Q K^T (3-pass) ----
        float sacc[8][4];
#pragma unroll
        for (int nt = 0; nt < 8; nt++)
#pragma unroll
            for (int q = 0; q < 4; q++) sacc[nt][q] = 0.f;

#pragma unroll
        for (int ks = 0; ks < 4; ks++) {
            uint32_t offA = (uint32_t)((wid * 16 + a_row) * AST + ks * 16 + a_col) * 2;
            uint32_t ah0, ah1, ah2, ah3, al0, al1, al2, al3;
            LDSM_X4(ah0, ah1, ah2, ah3, qhi_b + offA);
            LDSM_X4(al0, al1, al2, al3, qlo_b + offA);
            uint32_t bhf[4][4], blf[4][4];
#pragma unroll
            for (int p = 0; p < 4; p++) {
                uint32_t offB = (uint32_t)((p * 16 + b_row) * AST + ks * 16 + b_col) * 2;
                LDSM_X4(bhf[p][0], bhf[p][1], bhf[p][2], bhf[p][3], khi_b + offB);
                LDSM_X4(blf[p][0], blf[p][1], blf[p][2], blf[p][3], klo_b + offB);
            }
#pragma unroll
            for (int p = 0; p < 4; p++)
#pragma unroll
                for (int t = 0; t < 2; t++) {
                    const int nt = p * 2 + t;
                    MMA16816(sacc[nt], ah0, ah1, ah2, ah3, bhf[p][t * 2], bhf[p][t * 2 + 1]);
                    MMA16816(sacc[nt], ah0, ah1, ah2, ah3, blf[p][t * 2], blf[p][t * 2 + 1]);
                    MMA16816(sacc[nt], al0, al1, al2, al3, bhf[p][t * 2], bhf[p][t * 2 + 1]);
                }
        }

        // ---- softmax ----
        const bool need_mask = (j0 >= 2 * qt);
#pragma unroll
        for (int hf = 0; hf < 2; hf++) {
            const int qrow = qt * 128 + wid * 16 + (lane >> 2) + hf * 8;
            float mx = -1e30f;
#pragma unroll
            for (int nt = 0; nt < 8; nt++)
#pragma unroll
                for (int u = 0; u < 2; u++) {
                    float v = sacc[nt][hf * 2 + u] * 0.125f;
                    if (need_mask && (j0 * 64 + nt * 8 + 2 * (lane & 3) + u > qrow)) v = -1e30f;
                    sacc[nt][hf * 2 + u] = v;
                    mx = fmaxf(mx, v);
                }
            mx = fmaxf(mx, __shfl_xor_sync(0xffffffffu, mx, 1));
            mx = fmaxf(mx, __shfl_xor_sync(0xffffffffu, mx, 2));
            float mnew = fmaxf(m[hf], mx);
            float corr = __expf(m[hf] - mnew);
            m[hf] = mnew;
            float ls = 0.f;
#pragma unroll
            for (int nt = 0; nt < 8; nt++)
#pragma unroll
                for (int u = 0; u < 2; u++) {
                    float p = __expf(sacc[nt][hf * 2 + u] - mnew);
                    sacc[nt][hf * 2 + u] = p;
                    ls += p;
                }
            ls += __shfl_xor_sync(0xffffffffu, ls, 1);
            ls += __shfl_xor_sync(0xffffffffu, ls, 2);
            l[hf] = l[hf] * corr + ls;
#pragma unroll
            for (int nt = 0; nt < 8; nt++)
#pragma unroll
                for (int u = 0; u < 2; u++) o[nt][hf * 2 + u] *= corr;
        }

        // ---- O += P V ----
#pragma unroll
        for (int ks = 0; ks < 4; ks++) {
            uint32_t a0h = f2h2(sacc[2 * ks][0], sacc[2 * ks][1]);
            uint32_t a1h = f2h2(sacc[2 * ks][2], sacc[2 * ks][3]);
            uint32_t a2h = f2h2(sacc[2 * ks + 1][0], sacc[2 * ks + 1][1]);
            uint32_t a3h = f2h2(sacc[2 * ks + 1][2], sacc[2 * ks + 1][3]);
            uint32_t a0l = f2h2_lo(sacc[2 * ks][0], sacc[2 * ks][1], a0h);
            uint32_t a1l = f2h2_lo(sacc[2 * ks][2], sacc[2 * ks][3], a1h);
            uint32_t a2l = f2h2_lo(sacc[2 * ks + 1][0], sacc[2 * ks + 1][1], a2h);
            uint32_t a3l = f2h2_lo(sacc[2 * ks + 1][2], sacc[2 * ks + 1][3], a3h);
#pragma unroll
            for (int p = 0; p < 4; p++) {
                uint32_t offV = (uint32_t)((ks * 16 + t_row) * AST + p * 16 + t_col) * 2;
                uint32_t bh0, bh1, bh2, bh3, bl0, bl1, bl2, bl3;
                LDSM_X4_T(bh0, bh1, bh2, bh3, vhi_b + offV);
                LDSM_X4_T(bl0, bl1, bl2, bl3, vlo_b + offV);
                MMA16816(o[p * 2 + 0], a0h, a1h, a2h, a3h, bh0, bh1);
                MMA16816(o[p * 2 + 0], a0h, a1h, a2h, a3h, bl0, bl1);
                MMA16816(o[p * 2 + 0], a0l, a1l, a2l, a3l, bh0, bh1);
                MMA16816(o[p * 2 + 1], a0h, a1h, a2h, a3h, bh2, bh3);
                MMA16816(o[p * 2 + 1], a0h, a1h, a2h, a3h, bl2, bl3);
                MMA16816(o[p * 2 + 1], a0l, a1l, a2l, a3l, bh2, bh3);
            }
        }
    }

    // Epilogue: y -> hi/lo halves
    float inv0 = 1.f / l[0], inv1 = 1.f / l[1];
#pragma unroll
    for (int nt = 0; nt < 8; nt++) {
        const int row = qt * 128 + wid * 16 + (lane >> 2);
        const int col = h * HD_ + nt * 8 + 2 * (lane & 3);
#pragma unroll
        for (int rr = 0; rr < 2; rr++) {
            float inv = rr ? inv1 : inv0;
            float v0 = o[nt][rr * 2] * inv, v1 = o[nt][rr * 2 + 1] * inv;
            size_t idx = ((size_t)b * T_ + row + rr * 8) * D_ + col;
            uint32_t hi = f2h2(v0, v1);
            uint32_t lo = f2h2_lo(v0, v1, hi);
            *(uint32_t*)(g_yhi + idx) = hi;
            *(uint32_t*)(g_ylo + idx) = lo;
        }
    }
}

// ---------------------------------------------------------------------------
extern "C" void kernel_launch(void* const* d_in, const int* in_sizes, int n_in,
                              void* d_out, int out_size)
{
    const float* x      = (const float*)d_in[0];
    const float* w_qkv  = (const float*)d_in[1];
    const float* w_proj = (const float*)d_in[2];
    float* out = (float*)d_out;

    static bool attr_set = false;
    if (!attr_set) {
        cudaFuncSetAttribute(attn_hmma, cudaFuncAttributeMaxDynamicSharedMemorySize,
                             ATTN_SMEM);
        cudaFuncSetAttribute(hmma_gemm<3 * D_, D_, 1>,
                             cudaFuncAttributeMaxDynamicSharedMemorySize, GK_SMEM);
        cudaFuncSetAttribute(hmma_gemm<D_, D_, 0>,
                             cudaFuncAttributeMaxDynamicSharedMemorySize, GK_SMEM);
        attr_set = true;
    }

    __half *xhi, *xlo, *wqh, *wql, *wph, *wpl, *yhi, *ylo, *qkvh, *qkvl;
    cudaGetSymbolAddress((void**)&xhi, g_xhi);
    cudaGetSymbolAddress((void**)&xlo, g_xlo);
    cudaGetSymbolAddress((void**)&wqh, g_wqkvhi);
    cudaGetSymbolAddress((void**)&wql, g_wqkvlo);
    cudaGetSymbolAddress((void**)&wph, g_wphi);
    cudaGetSymbolAddress((void**)&wpl, g_wplo);
    cudaGetSymbolAddress((void**)&yhi, g_yhi);
    cudaGetSymbolAddress((void**)&ylo, g_ylo);
    cudaGetSymbolAddress((void**)&qkvh, g_qkvhi);
    cudaGetSymbolAddress((void**)&qkvl, g_qkvlo);

    // Split inputs
    {
        int n4 = M_ROWS * D_ / 4;
        split_kernel<<<(n4 + 255) / 256, 256>>>(x, xhi, xlo, n4);
        n4 = 3 * D_ * D_ / 4;
        split_kernel<<<(n4 + 255) / 256, 256>>>(w_qkv, wqh, wql, n4);
        n4 = D_ * D_ / 4;
        split_kernel<<<(n4 + 255) / 256, 256>>>(w_proj, wph, wpl, n4);
    }

    // QKV GEMM -> hi/lo halves
    {
        dim3 grid(3 * D_ / 128, M_ROWS / 128);
        hmma_gemm<3 * D_, D_, 1><<<grid, 128, GK_SMEM>>>(xhi, xlo, wqh, wql,
                                                         nullptr, qkvh, qkvl);
    }

    // HMMA attention -> y hi/lo
    {
        dim3 grid(T_ / 128, B_ * H_);
        attn_hmma<<<grid, 256, ATTN_SMEM>>>();
    }

    // Proj GEMM -> fp32 out
    {
        dim3 grid(D_ / 128, M_ROWS / 128);
        hmma_gemm<D_, D_, 0><<<grid, 128, GK_SMEM>>>(yhi, ylo, wph, wpl,
                                                     out, nullptr, nullptr);
    }
}